// round 8
// baseline (speedup 1.0000x reference)
#include <cuda_runtime.h>
#include <cuda_bf16.h>
#include <math.h>

// ---------------------------------------------------------------------------
// Problem constants
// ---------------------------------------------------------------------------
#define MTOK   8192
#define DIMC   768
#define HEADS  12
#define HD     64
#define KPARTS 64
#define MLPH   3072
#define NTOK   1024
#define BATCH  8
#define X_ELEMS (MTOK * DIMC)

#define ZCHUNK 48

typedef __nv_bfloat16 bf16;
typedef __nv_bfloat162 bf162;

// ---------------------------------------------------------------------------
// Scratch: fp32 + bf16-pair buffers (hi at [0..N), lo at [N..2N))
// ---------------------------------------------------------------------------
__device__ float g_scores[(long long)ZCHUNK * NTOK * NTOK];   // fp32, reused in-place as pair
__device__ float g_y   [MTOK * DIMC];
__device__ float g_xr  [MTOK * DIMC];
__device__ float g_rinv[MTOK];
__device__ float g_pinv[KPARTS];

__device__ bf16 g_n1p [2 * MTOK * DIMC];
__device__ bf16 g_qkvp[2 * MTOK * 3 * DIMC];
__device__ bf16 g_attp[2 * MTOK * DIMC];
__device__ bf16 g_h1p [2 * MTOK * KPARTS];
__device__ bf16 g_zinp[2 * MTOK * DIMC];
__device__ bf16 g_hp  [2 * MTOK * MLPH];
__device__ bf16 g_dmp [2 * MTOK * KPARTS];

// weight pool
#define W_QKV   (3*DIMC*DIMC)
#define W_PROJ  (DIMC*DIMC)
#define W_CQKV  (3*DIMC*DIMC)
#define W_CPROJ (DIMC*DIMC)
#define W_CPFC1 (KPARTS*KPARTS)
#define W_CPFC2 (DIMC*KPARTS)
#define W_FC1   (MLPH*DIMC)
#define W_FC2   (DIMC*MLPH)
#define W_P     (KPARTS*DIMC)
#define O_QKV   0
#define O_PROJ  (O_QKV  + 2*W_QKV)
#define O_CQKV  (O_PROJ + 2*W_PROJ)
#define O_CPROJ (O_CQKV + 2*W_CQKV)
#define O_CPFC1 (O_CPROJ+ 2*W_CPROJ)
#define O_CPFC2 (O_CPFC1+ 2*W_CPFC1)
#define O_FC1   (O_CPFC2+ 2*W_CPFC2)
#define O_FC2   (O_FC1  + 2*W_FC1)
#define O_P     (O_FC2  + 2*W_FC2)
#define W_TOTAL (O_P    + 2*W_P)
__device__ bf16 g_wpool[W_TOTAL];

// ---------------------------------------------------------------------------
// Helpers
// ---------------------------------------------------------------------------
__device__ __forceinline__ void fsplit(float v, bf16& h, bf16& l) {
    h = __float2bfloat16(v);
    l = __float2bfloat16(v - __bfloat162float(h));
}

__device__ __forceinline__ float blk_sum(float v, float* sbuf) {
    #pragma unroll
    for (int o = 16; o; o >>= 1) v += __shfl_xor_sync(0xffffffffu, v, o);
    if ((threadIdx.x & 31) == 0) sbuf[threadIdx.x >> 5] = v;
    __syncthreads();
    if (threadIdx.x == 0) {
        float r = sbuf[0];
        int nw = blockDim.x >> 5;
        for (int i = 1; i < nw; i++) r += sbuf[i];
        sbuf[0] = r;
    }
    __syncthreads();
    float r = sbuf[0];
    __syncthreads();
    return r;
}

__device__ __forceinline__ float blk_max(float v, float* sbuf) {
    #pragma unroll
    for (int o = 16; o; o >>= 1) v = fmaxf(v, __shfl_xor_sync(0xffffffffu, v, o));
    if ((threadIdx.x & 31) == 0) sbuf[threadIdx.x >> 5] = v;
    __syncthreads();
    if (threadIdx.x == 0) {
        float r = sbuf[0];
        int nw = blockDim.x >> 5;
        for (int i = 1; i < nw; i++) r = fmaxf(r, sbuf[i]);
        sbuf[0] = r;
    }
    __syncthreads();
    float r = sbuf[0];
    __syncthreads();
    return r;
}

// ---------------------------------------------------------------------------
// Elementwise split (weights)
// ---------------------------------------------------------------------------
__global__ void split_k(const float* __restrict__ src, bf16* __restrict__ hi,
                        bf16* __restrict__ lo, int n) {
    for (int i = blockIdx.x * blockDim.x + threadIdx.x; i < n; i += gridDim.x * blockDim.x) {
        float v = src[i];
        bf16 h, l; fsplit(v, h, l);
        hi[i] = h; lo[i] = l;
    }
}

// ---------------------------------------------------------------------------
// LayerNorm -> bf16 pair (+ optional 1/||row||)
// ---------------------------------------------------------------------------
__global__ void ln_kernel(const float* __restrict__ x, const float* __restrict__ g,
                          const float* __restrict__ b, bf16* __restrict__ outh,
                          bf16* __restrict__ outl, float* __restrict__ rinv) {
    __shared__ float sbuf[8];
    long long row = blockIdx.x;
    const float* xr = x + row * DIMC;
    float v[3];
    float s = 0.f;
    #pragma unroll
    for (int k = 0; k < 3; k++) { v[k] = xr[threadIdx.x + 256 * k]; s += v[k]; }
    float mu = blk_sum(s, sbuf) * (1.f / DIMC);
    float s2 = 0.f;
    #pragma unroll
    for (int k = 0; k < 3; k++) { float d = v[k] - mu; s2 += d * d; }
    float var = blk_sum(s2, sbuf) * (1.f / DIMC);
    float rs = rsqrtf(var + 1e-5f);
    float sq = 0.f;
    #pragma unroll
    for (int k = 0; k < 3; k++) {
        int c = threadIdx.x + 256 * k;
        float yv = (v[k] - mu) * rs * g[c] + b[c];
        bf16 h, l; fsplit(yv, h, l);
        outh[row * DIMC + c] = h;
        outl[row * DIMC + c] = l;
        sq += yv * yv;
    }
    if (rinv) {
        float nn = blk_sum(sq, sbuf);
        if (threadIdx.x == 0) rinv[row] = 1.f / sqrtf(nn);
    }
}

__global__ void rownorm_kernel(const float* __restrict__ P, float* __restrict__ pinv) {
    __shared__ float sbuf[8];
    const float* r = P + (long long)blockIdx.x * DIMC;
    float s = 0.f;
    for (int k = threadIdx.x; k < DIMC; k += 256) { float v = r[k]; s += v * v; }
    s = blk_sum(s, sbuf);
    if (threadIdx.x == 0) pinv[blockIdx.x] = 1.f / sqrtf(s);
}

// ---------------------------------------------------------------------------
// Softmax over 1024 cols; writes bf16 pair IN PLACE over the fp32 row
// (row layout after: hi[0..1023], lo[1024..2047] as bf16).
// Safe: all loads complete before the block reductions' syncthreads.
// ---------------------------------------------------------------------------
__global__ void softmax1024(float* __restrict__ S) {
    __shared__ float sbuf[8];
    float* rowf = S + (long long)blockIdx.x * NTOK;
    float4 v = ((float4*)rowf)[threadIdx.x];
    float mx = fmaxf(fmaxf(v.x, v.y), fmaxf(v.z, v.w));
    mx = blk_max(mx, sbuf);
    v.x = expf(v.x - mx); v.y = expf(v.y - mx);
    v.z = expf(v.z - mx); v.w = expf(v.w - mx);
    float s = blk_sum(v.x + v.y + v.z + v.w, sbuf);
    float inv = 1.f / s;
    v.x *= inv; v.y *= inv; v.z *= inv; v.w *= inv;
    bf16* rowh = (bf16*)rowf;
    int c = threadIdx.x * 4;
    bf16 h0, l0, h1, l1, h2, l2, h3, l3;
    fsplit(v.x, h0, l0); fsplit(v.y, h1, l1);
    fsplit(v.z, h2, l2); fsplit(v.w, h3, l3);
    *(bf162*)&rowh[c]            = __halves2bfloat162(h0, h1);
    *(bf162*)&rowh[c + 2]        = __halves2bfloat162(h2, h3);
    *(bf162*)&rowh[NTOK + c]     = __halves2bfloat162(l0, l1);
    *(bf162*)&rowh[NTOK + c + 2] = __halves2bfloat162(l2, l3);
}

// ---------------------------------------------------------------------------
// Pair-input bf16x3 tensor-core GEMM with ldmatrix fragment loads.
//   C = alpha * (Ahi+Alo)(Bhi+Blo)^(T?) dropping lo*lo.
// TRB=true : B stored [N][K];  TRB=false: B stored [K][N].
// EPI: 0 none, 1 GELU, 2 row*col scale, 3 residual add(s).
// OUTM: 0 fp32 C, 1 bf16 pair C, 2 both.
// ---------------------------------------------------------------------------
__device__ __forceinline__ void mma16816(float* d, const unsigned* a, const unsigned* b) {
    asm volatile(
        "mma.sync.aligned.m16n8k16.row.col.f32.bf16.bf16.f32 "
        "{%0,%1,%2,%3}, {%4,%5,%6,%7}, {%8,%9}, {%0,%1,%2,%3};\n"
        : "+f"(d[0]), "+f"(d[1]), "+f"(d[2]), "+f"(d[3])
        : "r"(a[0]), "r"(a[1]), "r"(a[2]), "r"(a[3]), "r"(b[0]), "r"(b[1]));
}

__device__ __forceinline__ void ldsm4(unsigned& r0, unsigned& r1, unsigned& r2,
                                      unsigned& r3, unsigned addr) {
    asm volatile("ldmatrix.sync.aligned.m8n8.x4.shared.b16 {%0,%1,%2,%3}, [%4];"
                 : "=r"(r0), "=r"(r1), "=r"(r2), "=r"(r3) : "r"(addr));
}

template<int BM, int BN, int BK, int WGM, int WGN, int WM, int WN, bool TRB, int EPI, int OUTM>
__global__ void __launch_bounds__(WGM * WGN * 32, 2)
pgemm_k(const bf16* __restrict__ Ahi, const bf16* __restrict__ Alo,
        const bf16* __restrict__ Bhi, const bf16* __restrict__ Blo,
        float* __restrict__ Cf, bf16* __restrict__ Chi, bf16* __restrict__ Clo,
        int K, int lda, int ldb, int ldc, int NH, int zoff, int aLocal, int cLocal,
        long long sAb, long long sAh, long long sBb, long long sBh,
        long long sCb, long long sCh,
        float alpha, const float* __restrict__ bias,
        const float* __restrict__ res1, const float* __restrict__ res2,
        const float* __restrict__ rowscale, const float* __restrict__ colscale) {
    constexpr int NT = WGM * WGN * 32;
    constexpr int MF = WM / 16;
    constexpr int NF = WN / 8;
    constexpr int NB = WN / 16;
    constexpr int KP = BK + 8;
    static_assert(WGM * WM == BM && WGN * WN == BN && (WN % 16) == 0, "tile");

    __shared__ bf16 sAh_s[BM * KP], sAl_s[BM * KP];
    __shared__ bf16 sBh_s[BN * KP], sBl_s[BN * KP];

    const int tid = threadIdx.x;
    const int warp = tid >> 5, lane = tid & 31;
    const int g = lane >> 2, t = lane & 3;
    const int r16 = lane & 15, kh = (lane >> 4) * 8;
    const int wm0 = (warp / WGN) * WM, wn0 = (warp % WGN) * WN;
    const int bx = blockIdx.x, by = blockIdx.y;
    const int bzg = blockIdx.z + zoff;
    const int zb = bzg / NH, zh = bzg % NH;

    const long long aoff = (aLocal ? (long long)blockIdx.z * sAh
                                   : (long long)zb * sAb + (long long)zh * sAh)
                         + (long long)by * BM * lda;
    const long long boff = (long long)zb * sBb + (long long)zh * sBh
                         + (TRB ? (long long)bx * BN * ldb : (long long)(bx * BN));
    const long long coff = (cLocal ? (long long)blockIdx.z * sCh
                                   : (long long)zb * sCb + (long long)zh * sCh)
                         + (long long)by * BM * ldc + (long long)(bx * BN);

    const bf16* Abh = Ahi + aoff; const bf16* Abl = Alo + aoff;
    const bf16* Bbh = Bhi + boff; const bf16* Bbl = Blo + boff;

    const unsigned uAh = (unsigned)__cvta_generic_to_shared(sAh_s);
    const unsigned uAl = (unsigned)__cvta_generic_to_shared(sAl_s);
    const unsigned uBh = (unsigned)__cvta_generic_to_shared(sBh_s);
    const unsigned uBl = (unsigned)__cvta_generic_to_shared(sBl_s);

    unsigned aoffs[MF], boffs[NB];
    #pragma unroll
    for (int fm = 0; fm < MF; fm++)
        aoffs[fm] = ((wm0 + fm * 16 + r16) * KP + kh) * 2;
    #pragma unroll
    for (int nb = 0; nb < NB; nb++)
        boffs[nb] = ((wn0 + nb * 16 + r16) * KP + kh) * 2;

    float acc[MF][NF][4] = {};

    for (int k0 = 0; k0 < K; k0 += BK) {
        // ---- fill A (row-major [m][k], 16B vector copies) ----
        #pragma unroll
        for (int idx = tid; idx < BM * (BK / 8); idx += NT) {
            int row = idx / (BK / 8), c8 = idx % (BK / 8);
            const long long go = (long long)row * lda + k0 + 8 * c8;
            *(uint4*)&sAh_s[row * KP + 8 * c8] = *(const uint4*)(Abh + go);
            *(uint4*)&sAl_s[row * KP + 8 * c8] = *(const uint4*)(Abl + go);
        }
        // ---- fill B into [n][k] ----
        if (TRB) {
            #pragma unroll
            for (int idx = tid; idx < BN * (BK / 8); idx += NT) {
                int row = idx / (BK / 8), c8 = idx % (BK / 8);
                const long long go = (long long)row * ldb + k0 + 8 * c8;
                *(uint4*)&sBh_s[row * KP + 8 * c8] = *(const uint4*)(Bbh + go);
                *(uint4*)&sBl_s[row * KP + 8 * c8] = *(const uint4*)(Bbl + go);
            }
        } else {
            #pragma unroll
            for (int idx = tid; idx < BK * (BN / 8); idx += NT) {
                int kr = idx / (BN / 8), c8 = idx % (BN / 8);
                const long long go = (long long)(k0 + kr) * ldb + 8 * c8;
                union { uint4 u; bf16 h[8]; } vh, vl;
                vh.u = *(const uint4*)(Bbh + go);
                vl.u = *(const uint4*)(Bbl + go);
                #pragma unroll
                for (int j = 0; j < 8; j++) {
                    sBh_s[(8 * c8 + j) * KP + kr] = vh.h[j];
                    sBl_s[(8 * c8 + j) * KP + kr] = vl.h[j];
                }
            }
        }
        __syncthreads();

        #pragma unroll
        for (int ks = 0; ks < BK / 16; ks++) {
            const unsigned kb = ks * 32;   // 16 halves = 32 bytes
            unsigned Ar[MF][4], Bf[NF][2], Bf2[NF][2];
            // A_hi
            #pragma unroll
            for (int fm = 0; fm < MF; fm++)
                ldsm4(Ar[fm][0], Ar[fm][1], Ar[fm][2], Ar[fm][3], uAh + aoffs[fm] + kb);
            // B_hi
            #pragma unroll
            for (int nb = 0; nb < NB; nb++) {
                unsigned q0, q1, q2, q3;
                ldsm4(q0, q1, q2, q3, uBh + boffs[nb] + kb);
                Bf[2*nb][0] = q0; Bf[2*nb][1] = q2;
                Bf[2*nb+1][0] = q1; Bf[2*nb+1][1] = q3;
            }
            #pragma unroll
            for (int fm = 0; fm < MF; fm++)
                #pragma unroll
                for (int fn = 0; fn < NF; fn++)
                    mma16816(acc[fm][fn], Ar[fm], Bf[fn]);
            // B_lo ; hi*lo
            #pragma unroll
            for (int nb = 0; nb < NB; nb++) {
                unsigned q0, q1, q2, q3;
                ldsm4(q0, q1, q2, q3, uBl + boffs[nb] + kb);
                Bf2[2*nb][0] = q0; Bf2[2*nb][1] = q2;
                Bf2[2*nb+1][0] = q1; Bf2[2*nb+1][1] = q3;
            }
            #pragma unroll
            for (int fm = 0; fm < MF; fm++)
                #pragma unroll
                for (int fn = 0; fn < NF; fn++)
                    mma16816(acc[fm][fn], Ar[fm], Bf2[fn]);
            // A_lo ; lo*hi
            #pragma unroll
            for (int fm = 0; fm < MF; fm++)
                ldsm4(Ar[fm][0], Ar[fm][1], Ar[fm][2], Ar[fm][3], uAl + aoffs[fm] + kb);
            #pragma unroll
            for (int fm = 0; fm < MF; fm++)
                #pragma unroll
                for (int fn = 0; fn < NF; fn++)
                    mma16816(acc[fm][fn], Ar[fm], Bf[fn]);
        }
        __syncthreads();
    }

    // ---- epilogue ----
    #pragma unroll
    for (int fm = 0; fm < MF; fm++) {
        #pragma unroll
        for (int fn = 0; fn < NF; fn++) {
            #pragma unroll
            for (int hh = 0; hh < 2; hh++) {
                int lrow = wm0 + fm * 16 + g + hh * 8;
                long long m = (long long)by * BM + lrow;
                int lcol = wn0 + fn * 8 + t * 2;
                int n = bx * BN + lcol;
                float v0 = acc[fm][fn][hh * 2 + 0] * alpha;
                float v1 = acc[fm][fn][hh * 2 + 1] * alpha;
                if (bias) { v0 += bias[n]; v1 += bias[n + 1]; }
                if constexpr (EPI == 1) {
                    v0 = 0.5f * v0 * (1.f + erff(v0 * 0.70710678118654752f));
                    v1 = 0.5f * v1 * (1.f + erff(v1 * 0.70710678118654752f));
                }
                if constexpr (EPI == 2) {
                    float rsc = rowscale[m];
                    v0 *= rsc * colscale[n];
                    v1 *= rsc * colscale[n + 1];
                }
                long long cix = coff + (long long)lrow * ldc + lcol;
                if constexpr (EPI == 3) {
                    v0 += res1[cix]; v1 += res1[cix + 1];
                    if (res2) { v0 += res2[cix]; v1 += res2[cix + 1]; }
                }
                if constexpr (OUTM == 0 || OUTM == 2) {
                    float2 fv = make_float2(v0, v1);
                    *(float2*)&Cf[cix] = fv;
                }
                if constexpr (OUTM >= 1) {
                    bf16 h0, l0, h1, l1;
                    fsplit(v0, h0, l0); fsplit(v1, h1, l1);
                    *(bf162*)&Chi[cix] = __halves2bfloat162(h0, h1);
                    *(bf162*)&Clo[cix] = __halves2bfloat162(l0, l1);
                }
            }
        }
    }
}

// ---------------------------------------------------------------------------
// Launchers
// ---------------------------------------------------------------------------
template<bool TRB, int EPI, int OUTM>
static void run128(const bf16* Ah, const bf16* Al, const bf16* Bh, const bf16* Bl,
                   float* Cf, bf16* Chi, bf16* Clo,
                   int Mrows, int Ncols, int K, int lda, int ldb, int ldc,
                   int nbz, int NH, int zoff, int aLocal, int cLocal,
                   long long sAb, long long sAh, long long sBb, long long sBh,
                   long long sCb, long long sCh,
                   float alpha, const float* bias, const float* res1, const float* res2,
                   const float* rs, const float* cs) {
    dim3 grid(Ncols / 128, Mrows / 128, nbz);
    pgemm_k<128, 128, 32, 2, 4, 64, 32, TRB, EPI, OUTM><<<grid, 256>>>(
        Ah, Al, Bh, Bl, Cf, Chi, Clo, K, lda, ldb, ldc, NH, zoff, aLocal, cLocal,
        sAb, sAh, sBb, sBh, sCb, sCh, alpha, bias, res1, res2, rs, cs);
}

template<bool TRB, int EPI, int OUTM>
static void run64(const bf16* Ah, const bf16* Al, const bf16* Bh, const bf16* Bl,
                  float* Cf, bf16* Chi, bf16* Clo,
                  int Mrows, int Ncols, int K, int lda, int ldb, int ldc,
                  int nbz, int NH, int zoff, int aLocal, int cLocal,
                  long long sAb, long long sAh, long long sBb, long long sBh,
                  long long sCb, long long sCh,
                  float alpha, const float* bias, const float* res1, const float* res2,
                  const float* rs, const float* cs) {
    dim3 grid(Ncols / 64, Mrows / 128, nbz);
    pgemm_k<128, 64, 32, 2, 4, 64, 16, TRB, EPI, OUTM><<<grid, 256>>>(
        Ah, Al, Bh, Bl, Cf, Chi, Clo, K, lda, ldb, ldc, NH, zoff, aLocal, cLocal,
        sAb, sAh, sBb, sBh, sCb, sCh, alpha, bias, res1, res2, rs, cs);
}

// ---------------------------------------------------------------------------
// kernel_launch
// ---------------------------------------------------------------------------
extern "C" void kernel_launch(void* const* d_in, const int* in_sizes, int n_in,
                              void* d_out, int out_size) {
    const float* x        = (const float*)d_in[0];
    const float* ln1_g    = (const float*)d_in[1];
    const float* ln1_b    = (const float*)d_in[2];
    const float* qkv_w    = (const float*)d_in[3];
    const float* qkv_b    = (const float*)d_in[4];
    const float* proj_w   = (const float*)d_in[5];
    const float* proj_b   = (const float*)d_in[6];
    const float* c_qkv_w  = (const float*)d_in[7];
    const float* c_qkv_b  = (const float*)d_in[8];
    const float* c_proj_w = (const float*)d_in[9];
    const float* c_proj_b = (const float*)d_in[10];
    const float* cp_fc1_w = (const float*)d_in[11];
    const float* cp_fc1_b = (const float*)d_in[12];
    const float* cp_fc2_w = (const float*)d_in[13];
    const float* cp_fc2_b = (const float*)d_in[14];
    const float* P        = (const float*)d_in[15];
    const float* ln2_g    = (const float*)d_in[16];
    const float* ln2_b    = (const float*)d_in[17];
    const float* fc1_w    = (const float*)d_in[18];
    const float* fc1_b    = (const float*)d_in[19];
    const float* fc2_w    = (const float*)d_in[20];
    const float* fc2_b    = (const float*)d_in[21];

    float *scores, *y, *xr, *rinv, *pinv;
    bf16 *n1p, *qkvp, *attp, *h1p, *zinp, *hp, *dmp, *wpool;
    cudaGetSymbolAddress((void**)&scores, g_scores);
    cudaGetSymbolAddress((void**)&y,      g_y);
    cudaGetSymbolAddress((void**)&xr,     g_xr);
    cudaGetSymbolAddress((void**)&rinv,   g_rinv);
    cudaGetSymbolAddress((void**)&pinv,   g_pinv);
    cudaGetSymbolAddress((void**)&n1p,    g_n1p);
    cudaGetSymbolAddress((void**)&qkvp,   g_qkvp);
    cudaGetSymbolAddress((void**)&attp,   g_attp);
    cudaGetSymbolAddress((void**)&h1p,    g_h1p);
    cudaGetSymbolAddress((void**)&zinp,   g_zinp);
    cudaGetSymbolAddress((void**)&hp,     g_hp);
    cudaGetSymbolAddress((void**)&dmp,    g_dmp);
    cudaGetSymbolAddress((void**)&wpool,  g_wpool);

    bf16 *wqh = wpool + O_QKV,   *wql = wqh + W_QKV;
    bf16 *wph = wpool + O_PROJ,  *wpl = wph + W_PROJ;
    bf16 *wch = wpool + O_CQKV,  *wcl = wch + W_CQKV;
    bf16 *wcph = wpool + O_CPROJ,*wcpl = wcph + W_CPROJ;
    bf16 *wf1h = wpool + O_CPFC1,*wf1l = wf1h + W_CPFC1;
    bf16 *wf2h = wpool + O_CPFC2,*wf2l = wf2h + W_CPFC2;
    bf16 *wm1h = wpool + O_FC1,  *wm1l = wm1h + W_FC1;
    bf16 *wm2h = wpool + O_FC2,  *wm2l = wm2h + W_FC2;
    bf16 *wPh = wpool + O_P,     *wPl = wPh + W_P;

    bf16 *n1h = n1p,  *n1l = n1p + MTOK * DIMC;
    bf16 *qkvh = qkvp,*qkvl = qkvp + MTOK * 3 * DIMC;
    bf16 *atth = attp,*attl = attp + MTOK * DIMC;
    bf16 *h1h = h1p,  *h1l = h1p + MTOK * KPARTS;
    bf16 *zinh = zinp,*zinl = zinp + MTOK * DIMC;
    bf16 *hh = hp,    *hl = hp + MTOK * MLPH;
    bf16 *dmh = dmp,  *dml = dmp + MTOK * KPARTS;

    float* out_x = (float*)d_out;
    float* dmap  = (float*)d_out + X_ELEMS;

    const long long sTokQ = (long long)NTOK * 3 * DIMC;
    const long long sS    = (long long)NTOK * NTOK;
    const long long sAtt_b = (long long)NTOK * DIMC;

    // ---- weight splits (cheap, once per launch) ----
    split_k<<<512, 256>>>(qkv_w,    wqh,  wql,  W_QKV);
    split_k<<<256, 256>>>(proj_w,   wph,  wpl,  W_PROJ);
    split_k<<<512, 256>>>(c_qkv_w,  wch,  wcl,  W_CQKV);
    split_k<<<256, 256>>>(c_proj_w, wcph, wcpl, W_CPROJ);
    split_k<<<16,  256>>>(cp_fc1_w, wf1h, wf1l, W_CPFC1);
    split_k<<<64,  256>>>(cp_fc2_w, wf2h, wf2l, W_CPFC2);
    split_k<<<512, 256>>>(fc1_w,    wm1h, wm1l, W_FC1);
    split_k<<<512, 256>>>(fc2_w,    wm2h, wm2l, W_FC2);
    split_k<<<64,  256>>>(P,        wPh,  wPl,  W_P);

    // 1. LN1 -> n1 pair + rinv;  2. pinv
    ln_kernel<<<MTOK, 256>>>(x, ln1_g, ln1_b, n1h, n1l, rinv);
    rownorm_kernel<<<KPARTS, 256>>>(P, pinv);

    // 3. qkv = n1 @ qkv_w^T + b  -> pair
    run128<true, 0, 1>(n1h, n1l, wqh, wql, nullptr, qkvh, qkvl,
        MTOK, 3 * DIMC, DIMC, DIMC, DIMC, 3 * DIMC,
        1, 1, 0, 0, 0, 0, 0, 0, 0, 0, 0,
        1.f, qkv_b, nullptr, nullptr, nullptr, nullptr);

    // 4-6. attention #1
    for (int z0 = 0; z0 < BATCH * HEADS; z0 += ZCHUNK) {
        run128<true, 0, 0>(qkvh, qkvl, qkvh + DIMC, qkvl + DIMC,
            scores, nullptr, nullptr,
            NTOK, NTOK, HD, 3 * DIMC, 3 * DIMC, NTOK,
            ZCHUNK, HEADS, z0, 0, 1,
            sTokQ, HD, sTokQ, HD, 0, sS,
            0.125f, nullptr, nullptr, nullptr, nullptr, nullptr);
        softmax1024<<<ZCHUNK * NTOK, 256>>>(scores);
        run64<false, 0, 1>((bf16*)scores, (bf16*)scores + NTOK,
            qkvh + 2 * DIMC, qkvl + 2 * DIMC,
            nullptr, atth, attl,
            NTOK, HD, NTOK, 2 * NTOK, 3 * DIMC, DIMC,
            ZCHUNK, HEADS, z0, 1, 0,
            0, 2 * sS, sTokQ, HD, sAtt_b, HD,
            1.f, nullptr, nullptr, nullptr, nullptr, nullptr);
    }

    // 7. y = att @ proj_w^T + b  (fp32)
    run128<true, 0, 0>(atth, attl, wph, wpl, y, nullptr, nullptr,
        MTOK, DIMC, DIMC, DIMC, DIMC, DIMC,
        1, 1, 0, 0, 0, 0, 0, 0, 0, 0, 0,
        1.f, proj_b, nullptr, nullptr, nullptr, nullptr);
    // 8. dmap = cosine(n1, P) -> fp32 out + pair
    run64<true, 2, 2>(n1h, n1l, wPh, wPl, dmap, dmh, dml,
        MTOK, KPARTS, DIMC, DIMC, DIMC, KPARTS,
        1, 1, 0, 0, 0, 0, 0, 0, 0, 0, 0,
        1.f, nullptr, nullptr, nullptr, rinv, pinv);
    // 9. h1 = gelu(dmap @ cp_fc1_w^T + b) -> pair
    run64<true, 1, 1>(dmh, dml, wf1h, wf1l, nullptr, h1h, h1l,
        MTOK, KPARTS, KPARTS, KPARTS, KPARTS, KPARTS,
        1, 1, 0, 0, 0, 0, 0, 0, 0, 0, 0,
        1.f, cp_fc1_b, nullptr, nullptr, nullptr, nullptr);
    // 10. zin = h1 @ cp_fc2_w^T + b -> pair
    run128<true, 0, 1>(h1h, h1l, wf2h, wf2l, nullptr, zinh, zinl,
        MTOK, DIMC, KPARTS, KPARTS, KPARTS, DIMC,
        1, 1, 0, 0, 0, 0, 0, 0, 0, 0, 0,
        1.f, cp_fc2_b, nullptr, nullptr, nullptr, nullptr);
    // 11. c_qkv -> pair (reuse qkv)
    run128<true, 0, 1>(zinh, zinl, wch, wcl, nullptr, qkvh, qkvl,
        MTOK, 3 * DIMC, DIMC, DIMC, DIMC, 3 * DIMC,
        1, 1, 0, 0, 0, 0, 0, 0, 0, 0, 0,
        1.f, c_qkv_b, nullptr, nullptr, nullptr, nullptr);

    // 12-14. attention #2
    for (int z0 = 0; z0 < BATCH * HEADS; z0 += ZCHUNK) {
        run128<true, 0, 0>(qkvh, qkvl, qkvh + DIMC, qkvl + DIMC,
            scores, nullptr, nullptr,
            NTOK, NTOK, HD, 3 * DIMC, 3 * DIMC, NTOK,
            ZCHUNK, HEADS, z0, 0, 1,
            sTokQ, HD, sTokQ, HD, 0, sS,
            0.125f, nullptr, nullptr, nullptr, nullptr, nullptr);
        softmax1024<<<ZCHUNK * NTOK, 256>>>(scores);
        run64<false, 0, 1>((bf16*)scores, (bf16*)scores + NTOK,
            qkvh + 2 * DIMC, qkvl + 2 * DIMC,
            nullptr, atth, attl,
            NTOK, HD, NTOK, 2 * NTOK, 3 * DIMC, DIMC,
            ZCHUNK, HEADS, z0, 1, 0,
            0, 2 * sS, sTokQ, HD, sAtt_b, HD,
            1.f, nullptr, nullptr, nullptr, nullptr, nullptr);
    }

    // 15. xr = att @ c_proj_w^T + b + x + y
    run128<true, 3, 0>(atth, attl, wcph, wcpl, xr, nullptr, nullptr,
        MTOK, DIMC, DIMC, DIMC, DIMC, DIMC,
        1, 1, 0, 0, 0, 0, 0, 0, 0, 0, 0,
        1.f, c_proj_b, x, y, nullptr, nullptr);
    // 16. LN2 -> n1 pair
    ln_kernel<<<MTOK, 256>>>(xr, ln2_g, ln2_b, n1h, n1l, nullptr);
    // 17. h = gelu(n1 @ fc1_w^T + b) -> pair
    run128<true, 1, 1>(n1h, n1l, wm1h, wm1l, nullptr, hh, hl,
        MTOK, MLPH, DIMC, DIMC, DIMC, MLPH,
        1, 1, 0, 0, 0, 0, 0, 0, 0, 0, 0,
        1.f, fc1_b, nullptr, nullptr, nullptr, nullptr);
    // 18. out_x = h @ fc2_w^T + b + xr
    run128<true, 3, 0>(hh, hl, wm2h, wm2l, out_x, nullptr, nullptr,
        MTOK, DIMC, MLPH, MLPH, MLPH, DIMC,
        1, 1, 0, 0, 0, 0, 0, 0, 0, 0, 0,
        1.f, fc2_b, xr, nullptr, nullptr, nullptr);
}

// round 9
// speedup vs baseline: 1.1482x; 1.1482x over previous
#include <cuda_runtime.h>
#include <cuda_bf16.h>
#include <math.h>

// ---------------------------------------------------------------------------
// Problem constants
// ---------------------------------------------------------------------------
#define MTOK   8192
#define DIMC   768
#define HEADS  12
#define HD     64
#define KPARTS 64
#define MLPH   3072
#define NTOK   1024
#define BATCH  8
#define X_ELEMS (MTOK * DIMC)

#define ZCHUNK 48

typedef __nv_bfloat16 bf16;
typedef __nv_bfloat162 bf162;

// ---------------------------------------------------------------------------
// Scratch
// ---------------------------------------------------------------------------
__device__ float g_scores[(long long)ZCHUNK * NTOK * NTOK];
__device__ float g_y   [MTOK * DIMC];
__device__ float g_xr  [MTOK * DIMC];
__device__ float g_rinv[MTOK];
__device__ float g_pinv[KPARTS];

__device__ bf16 g_n1p [2 * MTOK * DIMC];
__device__ bf16 g_qkvp[2 * MTOK * 3 * DIMC];
__device__ bf16 g_attp[2 * MTOK * DIMC];
__device__ bf16 g_h1p [2 * MTOK * KPARTS];
__device__ bf16 g_zinp[2 * MTOK * DIMC];
__device__ bf16 g_hp  [2 * MTOK * MLPH];
__device__ bf16 g_dmp [2 * MTOK * KPARTS];

#define W_QKV   (3*DIMC*DIMC)
#define W_PROJ  (DIMC*DIMC)
#define W_CQKV  (3*DIMC*DIMC)
#define W_CPROJ (DIMC*DIMC)
#define W_CPFC1 (KPARTS*KPARTS)
#define W_CPFC2 (DIMC*KPARTS)
#define W_FC1   (MLPH*DIMC)
#define W_FC2   (DIMC*MLPH)
#define W_P     (KPARTS*DIMC)
#define O_QKV   0
#define O_PROJ  (O_QKV  + 2*W_QKV)
#define O_CQKV  (O_PROJ + 2*W_PROJ)
#define O_CPROJ (O_CQKV + 2*W_CQKV)
#define O_CPFC1 (O_CPROJ+ 2*W_CPROJ)
#define O_CPFC2 (O_CPFC1+ 2*W_CPFC1)
#define O_FC1   (O_CPFC2+ 2*W_CPFC2)
#define O_FC2   (O_FC1  + 2*W_FC1)
#define O_P     (O_FC2  + 2*W_FC2)
#define W_TOTAL (O_P    + 2*W_P)
__device__ bf16 g_wpool[W_TOTAL];

// ---------------------------------------------------------------------------
// Helpers
// ---------------------------------------------------------------------------
__device__ __forceinline__ void fsplit(float v, bf16& h, bf16& l) {
    h = __float2bfloat16(v);
    l = __float2bfloat16(v - __bfloat162float(h));
}

__device__ __forceinline__ float blk_sum(float v, float* sbuf) {
    #pragma unroll
    for (int o = 16; o; o >>= 1) v += __shfl_xor_sync(0xffffffffu, v, o);
    if ((threadIdx.x & 31) == 0) sbuf[threadIdx.x >> 5] = v;
    __syncthreads();
    if (threadIdx.x == 0) {
        float r = sbuf[0];
        int nw = blockDim.x >> 5;
        for (int i = 1; i < nw; i++) r += sbuf[i];
        sbuf[0] = r;
    }
    __syncthreads();
    float r = sbuf[0];
    __syncthreads();
    return r;
}

__device__ __forceinline__ float blk_max(float v, float* sbuf) {
    #pragma unroll
    for (int o = 16; o; o >>= 1) v = fmaxf(v, __shfl_xor_sync(0xffffffffu, v, o));
    if ((threadIdx.x & 31) == 0) sbuf[threadIdx.x >> 5] = v;
    __syncthreads();
    if (threadIdx.x == 0) {
        float r = sbuf[0];
        int nw = blockDim.x >> 5;
        for (int i = 1; i < nw; i++) r = fmaxf(r, sbuf[i]);
        sbuf[0] = r;
    }
    __syncthreads();
    float r = sbuf[0];
    __syncthreads();
    return r;
}

__global__ void split_k(const float* __restrict__ src, bf16* __restrict__ hi,
                        bf16* __restrict__ lo, int n) {
    for (int i = blockIdx.x * blockDim.x + threadIdx.x; i < n; i += gridDim.x * blockDim.x) {
        float v = src[i];
        bf16 h, l; fsplit(v, h, l);
        hi[i] = h; lo[i] = l;
    }
}

__global__ void ln_kernel(const float* __restrict__ x, const float* __restrict__ g,
                          const float* __restrict__ b, bf16* __restrict__ outh,
                          bf16* __restrict__ outl, float* __restrict__ rinv) {
    __shared__ float sbuf[8];
    long long row = blockIdx.x;
    const float* xr = x + row * DIMC;
    float v[3];
    float s = 0.f;
    #pragma unroll
    for (int k = 0; k < 3; k++) { v[k] = xr[threadIdx.x + 256 * k]; s += v[k]; }
    float mu = blk_sum(s, sbuf) * (1.f / DIMC);
    float s2 = 0.f;
    #pragma unroll
    for (int k = 0; k < 3; k++) { float d = v[k] - mu; s2 += d * d; }
    float var = blk_sum(s2, sbuf) * (1.f / DIMC);
    float rs = rsqrtf(var + 1e-5f);
    float sq = 0.f;
    #pragma unroll
    for (int k = 0; k < 3; k++) {
        int c = threadIdx.x + 256 * k;
        float yv = (v[k] - mu) * rs * g[c] + b[c];
        bf16 h, l; fsplit(yv, h, l);
        outh[row * DIMC + c] = h;
        outl[row * DIMC + c] = l;
        sq += yv * yv;
    }
    if (rinv) {
        float nn = blk_sum(sq, sbuf);
        if (threadIdx.x == 0) rinv[row] = 1.f / sqrtf(nn);
    }
}

__global__ void rownorm_kernel(const float* __restrict__ P, float* __restrict__ pinv) {
    __shared__ float sbuf[8];
    const float* r = P + (long long)blockIdx.x * DIMC;
    float s = 0.f;
    for (int k = threadIdx.x; k < DIMC; k += 256) { float v = r[k]; s += v * v; }
    s = blk_sum(s, sbuf);
    if (threadIdx.x == 0) pinv[blockIdx.x] = 1.f / sqrtf(s);
}

// Softmax; writes bf16 pair in place over the fp32 row (hi[0..1023], lo[1024..2047]).
__global__ void softmax1024(float* __restrict__ S) {
    __shared__ float sbuf[8];
    float* rowf = S + (long long)blockIdx.x * NTOK;
    float4 v = ((float4*)rowf)[threadIdx.x];
    float mx = fmaxf(fmaxf(v.x, v.y), fmaxf(v.z, v.w));
    mx = blk_max(mx, sbuf);
    v.x = expf(v.x - mx); v.y = expf(v.y - mx);
    v.z = expf(v.z - mx); v.w = expf(v.w - mx);
    float s = blk_sum(v.x + v.y + v.z + v.w, sbuf);
    float inv = 1.f / s;
    v.x *= inv; v.y *= inv; v.z *= inv; v.w *= inv;
    bf16* rowh = (bf16*)rowf;
    int c = threadIdx.x * 4;
    bf16 h0, l0, h1, l1, h2, l2, h3, l3;
    fsplit(v.x, h0, l0); fsplit(v.y, h1, l1);
    fsplit(v.z, h2, l2); fsplit(v.w, h3, l3);
    *(bf162*)&rowh[c]            = __halves2bfloat162(h0, h1);
    *(bf162*)&rowh[c + 2]        = __halves2bfloat162(h2, h3);
    *(bf162*)&rowh[NTOK + c]     = __halves2bfloat162(l0, l1);
    *(bf162*)&rowh[NTOK + c + 2] = __halves2bfloat162(l2, l3);
}

// ---------------------------------------------------------------------------
// MMA / ldmatrix / cp.async primitives
// ---------------------------------------------------------------------------
__device__ __forceinline__ void mma16816(float* d, const unsigned* a, const unsigned* b) {
    asm volatile(
        "mma.sync.aligned.m16n8k16.row.col.f32.bf16.bf16.f32 "
        "{%0,%1,%2,%3}, {%4,%5,%6,%7}, {%8,%9}, {%0,%1,%2,%3};\n"
        : "+f"(d[0]), "+f"(d[1]), "+f"(d[2]), "+f"(d[3])
        : "r"(a[0]), "r"(a[1]), "r"(a[2]), "r"(a[3]), "r"(b[0]), "r"(b[1]));
}

__device__ __forceinline__ void ldsm4(unsigned& r0, unsigned& r1, unsigned& r2,
                                      unsigned& r3, unsigned addr) {
    asm volatile("ldmatrix.sync.aligned.m8n8.x4.shared.b16 {%0,%1,%2,%3}, [%4];"
                 : "=r"(r0), "=r"(r1), "=r"(r2), "=r"(r3) : "r"(addr));
}

__device__ __forceinline__ void ldsm4t(unsigned& r0, unsigned& r1, unsigned& r2,
                                       unsigned& r3, unsigned addr) {
    asm volatile("ldmatrix.sync.aligned.m8n8.x4.trans.shared.b16 {%0,%1,%2,%3}, [%4];"
                 : "=r"(r0), "=r"(r1), "=r"(r2), "=r"(r3) : "r"(addr));
}

__device__ __forceinline__ void cpa16(unsigned saddr, const void* gaddr) {
    asm volatile("cp.async.cg.shared.global [%0], [%1], 16;\n"
                 :: "r"(saddr), "l"(gaddr));
}

// ---------------------------------------------------------------------------
// Pipelined (2-stage cp.async) pair-input bf16x3 tensor-core GEMM.
//   C = alpha * (Ahi+Alo)(Bhi+Blo)^(T?) dropping lo*lo.
// TRB=true : B [N][K] row-major (k-contig); smem [n][k], ldmatrix.
// TRB=false: B [K][N] row-major (n-contig); smem [k][n], ldmatrix.trans.
// EPI: 0 none, 1 GELU, 2 row*col scale, 3 residual add(s).
// OUTM: 0 fp32 C, 1 bf16 pair C, 2 both.
// ---------------------------------------------------------------------------
template<int BM, int BN, int BK, int WGM, int WGN, int WM, int WN, bool TRB, int EPI, int OUTM>
__global__ void __launch_bounds__(WGM * WGN * 32, 2)
pgemm_k(const bf16* __restrict__ Ahi, const bf16* __restrict__ Alo,
        const bf16* __restrict__ Bhi, const bf16* __restrict__ Blo,
        float* __restrict__ Cf, bf16* __restrict__ Chi, bf16* __restrict__ Clo,
        int K, int lda, int ldb, int ldc, int NH, int zoff, int aLocal, int cLocal,
        long long sAb, long long sAh, long long sBb, long long sBh,
        long long sCb, long long sCh,
        float alpha, const float* __restrict__ bias,
        const float* __restrict__ res1, const float* __restrict__ res2,
        const float* __restrict__ rowscale, const float* __restrict__ colscale) {
    constexpr int NT = WGM * WGN * 32;
    constexpr int MF = WM / 16;
    constexpr int NF = WN / 8;
    constexpr int NB = WN / 16;
    constexpr int KP = BK + 8;
    constexpr int BNP = BN + 8;
    constexpr int ASZ = BM * KP;
    constexpr int BSZ = TRB ? (BN * KP) : (BK * BNP);
    constexpr unsigned STGB = (unsigned)(2 * ASZ + 2 * BSZ) * 2u;   // bytes per stage
    constexpr unsigned OFF_AH = 0;
    constexpr unsigned OFF_AL = (unsigned)ASZ * 2u;
    constexpr unsigned OFF_BH = (unsigned)ASZ * 4u;
    constexpr unsigned OFF_BL = (unsigned)ASZ * 4u + (unsigned)BSZ * 2u;
    static_assert(WGM * WM == BM && WGN * WN == BN && (WN % 16) == 0, "tile");

    extern __shared__ bf16 smem_dyn[];
    const unsigned u0 = (unsigned)__cvta_generic_to_shared(smem_dyn);

    const int tid = threadIdx.x;
    const int warp = tid >> 5, lane = tid & 31;
    const int g = lane >> 2, t = lane & 3;
    const int r16 = lane & 15, kh = (lane >> 4) * 8;
    const int wm0 = (warp / WGN) * WM, wn0 = (warp % WGN) * WN;
    const int bx = blockIdx.x, by = blockIdx.y;
    const int bzg = blockIdx.z + zoff;
    const int zb = bzg / NH, zh = bzg % NH;

    const long long aoff = (aLocal ? (long long)blockIdx.z * sAh
                                   : (long long)zb * sAb + (long long)zh * sAh)
                         + (long long)by * BM * lda;
    const long long boff = (long long)zb * sBb + (long long)zh * sBh
                         + (TRB ? (long long)bx * BN * ldb : (long long)(bx * BN));
    const long long coff = (cLocal ? (long long)blockIdx.z * sCh
                                   : (long long)zb * sCb + (long long)zh * sCh)
                         + (long long)by * BM * ldc + (long long)(bx * BN);

    const bf16* Abh = Ahi + aoff; const bf16* Abl = Alo + aoff;
    const bf16* Bbh = Bhi + boff; const bf16* Bbl = Blo + boff;

    // ldmatrix source offsets (bytes, relative to each array base)
    unsigned aoffs[MF], boffs[NB];
    #pragma unroll
    for (int fm = 0; fm < MF; fm++)
        aoffs[fm] = (unsigned)((wm0 + fm * 16 + r16) * KP + kh) * 2u;
    if constexpr (TRB) {
        #pragma unroll
        for (int nb = 0; nb < NB; nb++)
            boffs[nb] = (unsigned)((wn0 + nb * 16 + r16) * KP + kh) * 2u;
    } else {
        const int koff = ((lane >> 4) & 1) * 8;
        const int noff = ((lane >> 3) & 1) * 8;
        #pragma unroll
        for (int nb = 0; nb < NB; nb++)
            boffs[nb] = (unsigned)(((lane & 7) + koff) * BNP + wn0 + nb * 16 + noff) * 2u;
    }

    float acc[MF][NF][4] = {};
    const int NKS = K / BK;

    auto fill = [&](int st, int k0) {
        const unsigned stb = u0 + (unsigned)st * STGB;
        #pragma unroll
        for (int idx = tid; idx < BM * (BK / 8); idx += NT) {
            int row = idx / (BK / 8), c8 = idx % (BK / 8);
            long long go = (long long)row * lda + k0 + 8 * c8;
            unsigned so = (unsigned)(row * KP + 8 * c8) * 2u;
            cpa16(stb + OFF_AH + so, Abh + go);
            cpa16(stb + OFF_AL + so, Abl + go);
        }
        if constexpr (TRB) {
            #pragma unroll
            for (int idx = tid; idx < BN * (BK / 8); idx += NT) {
                int row = idx / (BK / 8), c8 = idx % (BK / 8);
                long long go = (long long)row * ldb + k0 + 8 * c8;
                unsigned so = (unsigned)(row * KP + 8 * c8) * 2u;
                cpa16(stb + OFF_BH + so, Bbh + go);
                cpa16(stb + OFF_BL + so, Bbl + go);
            }
        } else {
            #pragma unroll
            for (int idx = tid; idx < BK * (BN / 8); idx += NT) {
                int kr = idx / (BN / 8), c8 = idx % (BN / 8);
                long long go = (long long)(k0 + kr) * ldb + 8 * c8;
                unsigned so = (unsigned)(kr * BNP + 8 * c8) * 2u;
                cpa16(stb + OFF_BH + so, Bbh + go);
                cpa16(stb + OFF_BL + so, Bbl + go);
            }
        }
        asm volatile("cp.async.commit_group;\n");
    };

    fill(0, 0);
    for (int i = 0; i < NKS; i++) {
        if (i + 1 < NKS) {
            fill((i + 1) & 1, (i + 1) * BK);
            asm volatile("cp.async.wait_group 1;\n");
        } else {
            asm volatile("cp.async.wait_group 0;\n");
        }
        __syncthreads();

        const unsigned stb = u0 + (unsigned)(i & 1) * STGB;
        #pragma unroll
        for (int ks = 0; ks < BK / 16; ks++) {
            const unsigned kbA = (unsigned)ks * 32u;
            unsigned Ar[MF][4], Bf[NF][2], Bf2[NF][2];
            // A_hi
            #pragma unroll
            for (int fm = 0; fm < MF; fm++)
                ldsm4(Ar[fm][0], Ar[fm][1], Ar[fm][2], Ar[fm][3],
                      stb + OFF_AH + aoffs[fm] + kbA);
            // B_hi
            #pragma unroll
            for (int nb = 0; nb < NB; nb++) {
                unsigned q0, q1, q2, q3;
                if constexpr (TRB)
                    ldsm4(q0, q1, q2, q3, stb + OFF_BH + boffs[nb] + kbA);
                else
                    ldsm4t(q0, q1, q2, q3, stb + OFF_BH + boffs[nb]
                           + (unsigned)(ks * 16 * BNP) * 2u);
                Bf[2*nb][0] = q0; Bf[2*nb+1][0] = q1;
                Bf[2*nb][1] = q2; Bf[2*nb+1][1] = q3;
            }
            #pragma unroll
            for (int fm = 0; fm < MF; fm++)
                #pragma unroll
                for (int fn = 0; fn < NF; fn++)
                    mma16816(acc[fm][fn], Ar[fm], Bf[fn]);
            // B_lo ; hi*lo
            #pragma unroll
            for (int nb = 0; nb < NB; nb++) {
                unsigned q0, q1, q2, q3;
                if constexpr (TRB)
                    ldsm4(q0, q1, q2, q3, stb + OFF_BL + boffs[nb] + kbA);
                else
                    ldsm4t(q0, q1, q2, q3, stb + OFF_BL + boffs[nb]
                           + (unsigned)(ks * 16 * BNP) * 2u);
                Bf2[2*nb][0] = q0; Bf2[2*nb+1][0] = q1;
                Bf2[2*nb][1] = q2; Bf2[2*nb+1][1] = q3;
            }
            #pragma unroll
            for (int fm = 0; fm < MF; fm++)
                #pragma unroll
                for (int fn = 0; fn < NF; fn++)
                    mma16816(acc[fm][fn], Ar[fm], Bf2[fn]);
            // A_lo ; lo*hi
            #pragma unroll
            for (int fm = 0; fm < MF; fm++)
                ldsm4(Ar[fm][0], Ar[fm][1], Ar[fm][2], Ar[fm][3],
                      stb + OFF_AL + aoffs[fm] + kbA);
            #pragma unroll
            for (int fm = 0; fm < MF; fm++)
                #pragma unroll
                for (int fn = 0; fn < NF; fn++)
                    mma16816(acc[fm][fn], Ar[fm], Bf[fn]);
        }
        __syncthreads();
    }

    // ---- epilogue ----
    #pragma unroll
    for (int fm = 0; fm < MF; fm++) {
        #pragma unroll
        for (int fn = 0; fn < NF; fn++) {
            #pragma unroll
            for (int hh = 0; hh < 2; hh++) {
                int lrow = wm0 + fm * 16 + g + hh * 8;
                long long m = (long long)by * BM + lrow;
                int lcol = wn0 + fn * 8 + t * 2;
                int n = bx * BN + lcol;
                float v0 = acc[fm][fn][hh * 2 + 0] * alpha;
                float v1 = acc[fm][fn][hh * 2 + 1] * alpha;
                if (bias) { v0 += bias[n]; v1 += bias[n + 1]; }
                if constexpr (EPI == 1) {
                    v0 = 0.5f * v0 * (1.f + erff(v0 * 0.70710678118654752f));
                    v1 = 0.5f * v1 * (1.f + erff(v1 * 0.70710678118654752f));
                }
                if constexpr (EPI == 2) {
                    float rsc = rowscale[m];
                    v0 *= rsc * colscale[n];
                    v1 *= rsc * colscale[n + 1];
                }
                long long cix = coff + (long long)lrow * ldc + lcol;
                if constexpr (EPI == 3) {
                    v0 += res1[cix]; v1 += res1[cix + 1];
                    if (res2) { v0 += res2[cix]; v1 += res2[cix + 1]; }
                }
                if constexpr (OUTM == 0 || OUTM == 2) {
                    float2 fv = make_float2(v0, v1);
                    *(float2*)&Cf[cix] = fv;
                }
                if constexpr (OUTM >= 1) {
                    bf16 h0, l0, h1, l1;
                    fsplit(v0, h0, l0); fsplit(v1, h1, l1);
                    *(bf162*)&Chi[cix] = __halves2bfloat162(h0, h1);
                    *(bf162*)&Clo[cix] = __halves2bfloat162(l0, l1);
                }
            }
        }
    }
}

// ---------------------------------------------------------------------------
// Launchers (dynamic smem, 2-stage)
// ---------------------------------------------------------------------------
template<bool TRB, int EPI, int OUTM>
static void run128(const bf16* Ah, const bf16* Al, const bf16* Bh, const bf16* Bl,
                   float* Cf, bf16* Chi, bf16* Clo,
                   int Mrows, int Ncols, int K, int lda, int ldb, int ldc,
                   int nbz, int NH, int zoff, int aLocal, int cLocal,
                   long long sAb, long long sAh, long long sBb, long long sBh,
                   long long sCb, long long sCh,
                   float alpha, const float* bias, const float* res1, const float* res2,
                   const float* rs, const float* cs) {
    auto kfn = pgemm_k<128, 128, 32, 2, 4, 64, 32, TRB, EPI, OUTM>;
    constexpr int ASZ = 128 * 40;
    constexpr int BSZ = TRB ? (128 * 40) : (32 * 136);
    constexpr int SMEM = 2 * (2 * ASZ + 2 * BSZ) * 2;
    cudaFuncSetAttribute((const void*)kfn,
                         cudaFuncAttributeMaxDynamicSharedMemorySize, SMEM);
    dim3 grid(Ncols / 128, Mrows / 128, nbz);
    kfn<<<grid, 256, SMEM>>>(
        Ah, Al, Bh, Bl, Cf, Chi, Clo, K, lda, ldb, ldc, NH, zoff, aLocal, cLocal,
        sAb, sAh, sBb, sBh, sCb, sCh, alpha, bias, res1, res2, rs, cs);
}

template<bool TRB, int EPI, int OUTM>
static void run64(const bf16* Ah, const bf16* Al, const bf16* Bh, const bf16* Bl,
                  float* Cf, bf16* Chi, bf16* Clo,
                  int Mrows, int Ncols, int K, int lda, int ldb, int ldc,
                  int nbz, int NH, int zoff, int aLocal, int cLocal,
                  long long sAb, long long sAh, long long sBb, long long sBh,
                  long long sCb, long long sCh,
                  float alpha, const float* bias, const float* res1, const float* res2,
                  const float* rs, const float* cs) {
    auto kfn = pgemm_k<128, 64, 32, 2, 4, 64, 16, TRB, EPI, OUTM>;
    constexpr int ASZ = 128 * 40;
    constexpr int BSZ = TRB ? (64 * 40) : (32 * 72);
    constexpr int SMEM = 2 * (2 * ASZ + 2 * BSZ) * 2;
    cudaFuncSetAttribute((const void*)kfn,
                         cudaFuncAttributeMaxDynamicSharedMemorySize, SMEM);
    dim3 grid(Ncols / 64, Mrows / 128, nbz);
    kfn<<<grid, 256, SMEM>>>(
        Ah, Al, Bh, Bl, Cf, Chi, Clo, K, lda, ldb, ldc, NH, zoff, aLocal, cLocal,
        sAb, sAh, sBb, sBh, sCb, sCh, alpha, bias, res1, res2, rs, cs);
}

// ---------------------------------------------------------------------------
// kernel_launch
// ---------------------------------------------------------------------------
extern "C" void kernel_launch(void* const* d_in, const int* in_sizes, int n_in,
                              void* d_out, int out_size) {
    const float* x        = (const float*)d_in[0];
    const float* ln1_g    = (const float*)d_in[1];
    const float* ln1_b    = (const float*)d_in[2];
    const float* qkv_w    = (const float*)d_in[3];
    const float* qkv_b    = (const float*)d_in[4];
    const float* proj_w   = (const float*)d_in[5];
    const float* proj_b   = (const float*)d_in[6];
    const float* c_qkv_w  = (const float*)d_in[7];
    const float* c_qkv_b  = (const float*)d_in[8];
    const float* c_proj_w = (const float*)d_in[9];
    const float* c_proj_b = (const float*)d_in[10];
    const float* cp_fc1_w = (const float*)d_in[11];
    const float* cp_fc1_b = (const float*)d_in[12];
    const float* cp_fc2_w = (const float*)d_in[13];
    const float* cp_fc2_b = (const float*)d_in[14];
    const float* P        = (const float*)d_in[15];
    const float* ln2_g    = (const float*)d_in[16];
    const float* ln2_b    = (const float*)d_in[17];
    const float* fc1_w    = (const float*)d_in[18];
    const float* fc1_b    = (const float*)d_in[19];
    const float* fc2_w    = (const float*)d_in[20];
    const float* fc2_b    = (const float*)d_in[21];

    float *scores, *y, *xr, *rinv, *pinv;
    bf16 *n1p, *qkvp, *attp, *h1p, *zinp, *hp, *dmp, *wpool;
    cudaGetSymbolAddress((void**)&scores, g_scores);
    cudaGetSymbolAddress((void**)&y,      g_y);
    cudaGetSymbolAddress((void**)&xr,     g_xr);
    cudaGetSymbolAddress((void**)&rinv,   g_rinv);
    cudaGetSymbolAddress((void**)&pinv,   g_pinv);
    cudaGetSymbolAddress((void**)&n1p,    g_n1p);
    cudaGetSymbolAddress((void**)&qkvp,   g_qkvp);
    cudaGetSymbolAddress((void**)&attp,   g_attp);
    cudaGetSymbolAddress((void**)&h1p,    g_h1p);
    cudaGetSymbolAddress((void**)&zinp,   g_zinp);
    cudaGetSymbolAddress((void**)&hp,     g_hp);
    cudaGetSymbolAddress((void**)&dmp,    g_dmp);
    cudaGetSymbolAddress((void**)&wpool,  g_wpool);

    bf16 *wqh = wpool + O_QKV,   *wql = wqh + W_QKV;
    bf16 *wph = wpool + O_PROJ,  *wpl = wph + W_PROJ;
    bf16 *wch = wpool + O_CQKV,  *wcl = wch + W_CQKV;
    bf16 *wcph = wpool + O_CPROJ,*wcpl = wcph + W_CPROJ;
    bf16 *wf1h = wpool + O_CPFC1,*wf1l = wf1h + W_CPFC1;
    bf16 *wf2h = wpool + O_CPFC2,*wf2l = wf2h + W_CPFC2;
    bf16 *wm1h = wpool + O_FC1,  *wm1l = wm1h + W_FC1;
    bf16 *wm2h = wpool + O_FC2,  *wm2l = wm2h + W_FC2;
    bf16 *wPh = wpool + O_P,     *wPl = wPh + W_P;

    bf16 *n1h = n1p,  *n1l = n1p + MTOK * DIMC;
    bf16 *qkvh = qkvp,*qkvl = qkvp + MTOK * 3 * DIMC;
    bf16 *atth = attp,*attl = attp + MTOK * DIMC;
    bf16 *h1h = h1p,  *h1l = h1p + MTOK * KPARTS;
    bf16 *zinh = zinp,*zinl = zinp + MTOK * DIMC;
    bf16 *hh = hp,    *hl = hp + MTOK * MLPH;
    bf16 *dmh = dmp,  *dml = dmp + MTOK * KPARTS;

    float* out_x = (float*)d_out;
    float* dmap  = (float*)d_out + X_ELEMS;

    const long long sTokQ = (long long)NTOK * 3 * DIMC;
    const long long sS    = (long long)NTOK * NTOK;
    const long long sAtt_b = (long long)NTOK * DIMC;

    // ---- weight splits ----
    split_k<<<512, 256>>>(qkv_w,    wqh,  wql,  W_QKV);
    split_k<<<256, 256>>>(proj_w,   wph,  wpl,  W_PROJ);
    split_k<<<512, 256>>>(c_qkv_w,  wch,  wcl,  W_CQKV);
    split_k<<<256, 256>>>(c_proj_w, wcph, wcpl, W_CPROJ);
    split_k<<<16,  256>>>(cp_fc1_w, wf1h, wf1l, W_CPFC1);
    split_k<<<64,  256>>>(cp_fc2_w, wf2h, wf2l, W_CPFC2);
    split_k<<<512, 256>>>(fc1_w,    wm1h, wm1l, W_FC1);
    split_k<<<512, 256>>>(fc2_w,    wm2h, wm2l, W_FC2);
    split_k<<<64,  256>>>(P,        wPh,  wPl,  W_P);

    // 1. LN1 -> n1 pair + rinv;  2. pinv
    ln_kernel<<<MTOK, 256>>>(x, ln1_g, ln1_b, n1h, n1l, rinv);
    rownorm_kernel<<<KPARTS, 256>>>(P, pinv);

    // 3. qkv = n1 @ qkv_w^T + b  -> pair
    run128<true, 0, 1>(n1h, n1l, wqh, wql, nullptr, qkvh, qkvl,
        MTOK, 3 * DIMC, DIMC, DIMC, DIMC, 3 * DIMC,
        1, 1, 0, 0, 0, 0, 0, 0, 0, 0, 0,
        1.f, qkv_b, nullptr, nullptr, nullptr, nullptr);

    // 4-6. attention #1
    for (int z0 = 0; z0 < BATCH * HEADS; z0 += ZCHUNK) {
        run128<true, 0, 0>(qkvh, qkvl, qkvh + DIMC, qkvl + DIMC,
            scores, nullptr, nullptr,
            NTOK, NTOK, HD, 3 * DIMC, 3 * DIMC, NTOK,
            ZCHUNK, HEADS, z0, 0, 1,
            sTokQ, HD, sTokQ, HD, 0, sS,
            0.125f, nullptr, nullptr, nullptr, nullptr, nullptr);
        softmax1024<<<ZCHUNK * NTOK, 256>>>(scores);
        run64<false, 0, 1>((bf16*)scores, (bf16*)scores + NTOK,
            qkvh + 2 * DIMC, qkvl + 2 * DIMC,
            nullptr, atth, attl,
            NTOK, HD, NTOK, 2 * NTOK, 3 * DIMC, DIMC,
            ZCHUNK, HEADS, z0, 1, 0,
            0, 2 * sS, sTokQ, HD, sAtt_b, HD,
            1.f, nullptr, nullptr, nullptr, nullptr, nullptr);
    }

    // 7. y = att @ proj_w^T + b  (fp32)
    run128<true, 0, 0>(atth, attl, wph, wpl, y, nullptr, nullptr,
        MTOK, DIMC, DIMC, DIMC, DIMC, DIMC,
        1, 1, 0, 0, 0, 0, 0, 0, 0, 0, 0,
        1.f, proj_b, nullptr, nullptr, nullptr, nullptr);
    // 8. dmap = cosine(n1, P) -> fp32 out + pair
    run64<true, 2, 2>(n1h, n1l, wPh, wPl, dmap, dmh, dml,
        MTOK, KPARTS, DIMC, DIMC, DIMC, KPARTS,
        1, 1, 0, 0, 0, 0, 0, 0, 0, 0, 0,
        1.f, nullptr, nullptr, nullptr, rinv, pinv);
    // 9. h1 = gelu(dmap @ cp_fc1_w^T + b) -> pair
    run64<true, 1, 1>(dmh, dml, wf1h, wf1l, nullptr, h1h, h1l,
        MTOK, KPARTS, KPARTS, KPARTS, KPARTS, KPARTS,
        1, 1, 0, 0, 0, 0, 0, 0, 0, 0, 0,
        1.f, cp_fc1_b, nullptr, nullptr, nullptr, nullptr);
    // 10. zin = h1 @ cp_fc2_w^T + b -> pair
    run128<true, 0, 1>(h1h, h1l, wf2h, wf2l, nullptr, zinh, zinl,
        MTOK, DIMC, KPARTS, KPARTS, KPARTS, DIMC,
        1, 1, 0, 0, 0, 0, 0, 0, 0, 0, 0,
        1.f, cp_fc2_b, nullptr, nullptr, nullptr, nullptr);
    // 11. c_qkv -> pair (reuse qkv)
    run128<true, 0, 1>(zinh, zinl, wch, wcl, nullptr, qkvh, qkvl,
        MTOK, 3 * DIMC, DIMC, DIMC, DIMC, 3 * DIMC,
        1, 1, 0, 0, 0, 0, 0, 0, 0, 0, 0,
        1.f, c_qkv_b, nullptr, nullptr, nullptr, nullptr);

    // 12-14. attention #2
    for (int z0 = 0; z0 < BATCH * HEADS; z0 += ZCHUNK) {
        run128<true, 0, 0>(qkvh, qkvl, qkvh + DIMC, qkvl + DIMC,
            scores, nullptr, nullptr,
            NTOK, NTOK, HD, 3 * DIMC, 3 * DIMC, NTOK,
            ZCHUNK, HEADS, z0, 0, 1,
            sTokQ, HD, sTokQ, HD, 0, sS,
            0.125f, nullptr, nullptr, nullptr, nullptr, nullptr);
        softmax1024<<<ZCHUNK * NTOK, 256>>>(scores);
        run64<false, 0, 1>((bf16*)scores, (bf16*)scores + NTOK,
            qkvh + 2 * DIMC, qkvl + 2 * DIMC,
            nullptr, atth, attl,
            NTOK, HD, NTOK, 2 * NTOK, 3 * DIMC, DIMC,
            ZCHUNK, HEADS, z0, 1, 0,
            0, 2 * sS, sTokQ, HD, sAtt_b, HD,
            1.f, nullptr, nullptr, nullptr, nullptr, nullptr);
    }

    // 15. xr = att @ c_proj_w^T + b + x + y
    run128<true, 3, 0>(atth, attl, wcph, wcpl, xr, nullptr, nullptr,
        MTOK, DIMC, DIMC, DIMC, DIMC, DIMC,
        1, 1, 0, 0, 0, 0, 0, 0, 0, 0, 0,
        1.f, c_proj_b, x, y, nullptr, nullptr);
    // 16. LN2 -> n1 pair
    ln_kernel<<<MTOK, 256>>>(xr, ln2_g, ln2_b, n1h, n1l, nullptr);
    // 17. h = gelu(n1 @ fc1_w^T + b) -> pair
    run128<true, 1, 1>(n1h, n1l, wm1h, wm1l, nullptr, hh, hl,
        MTOK, MLPH, DIMC, DIMC, DIMC, MLPH,
        1, 1, 0, 0, 0, 0, 0, 0, 0, 0, 0,
        1.f, fc1_b, nullptr, nullptr, nullptr, nullptr);
    // 18. out_x = h @ fc2_w^T + b + xr
    run128<true, 3, 0>(hh, hl, wm2h, wm2l, out_x, nullptr, nullptr,
        MTOK, DIMC, MLPH, MLPH, MLPH, DIMC,
        1, 1, 0, 0, 0, 0, 0, 0, 0, 0, 0,
        1.f, fc2_b, xr, nullptr, nullptr, nullptr);
}

// round 12
// speedup vs baseline: 1.3766x; 1.1989x over previous
#include <cuda_runtime.h>
#include <cuda_bf16.h>
#include <math.h>

// ---------------------------------------------------------------------------
// Problem constants
// ---------------------------------------------------------------------------
#define MTOK   8192
#define DIMC   768
#define HEADS  12
#define HD     64
#define KPARTS 64
#define MLPH   3072
#define NTOK   1024
#define BATCH  8
#define X_ELEMS (MTOK * DIMC)

typedef __nv_bfloat16 bf16;
typedef __nv_bfloat162 bf162;

// ---------------------------------------------------------------------------
// Scratch
// ---------------------------------------------------------------------------
__device__ float g_y   [MTOK * DIMC];
__device__ float g_xr  [MTOK * DIMC];
__device__ float g_rinv[MTOK];
__device__ float g_pinv[KPARTS];

__device__ bf16 g_n1p [2 * MTOK * DIMC];
__device__ bf16 g_qkvp[2 * MTOK * 3 * DIMC];
__device__ bf16 g_attp[2 * MTOK * DIMC];
__device__ bf16 g_h1p [2 * MTOK * KPARTS];
__device__ bf16 g_zinp[2 * MTOK * DIMC];
__device__ bf16 g_hp  [2 * MTOK * MLPH];
__device__ bf16 g_dmp [2 * MTOK * KPARTS];

#define W_QKV   (3*DIMC*DIMC)
#define W_PROJ  (DIMC*DIMC)
#define W_CQKV  (3*DIMC*DIMC)
#define W_CPROJ (DIMC*DIMC)
#define W_CPFC1 (KPARTS*KPARTS)
#define W_CPFC2 (DIMC*KPARTS)
#define W_FC1   (MLPH*DIMC)
#define W_FC2   (DIMC*MLPH)
#define W_P     (KPARTS*DIMC)
#define O_QKV   0
#define O_PROJ  (O_QKV  + 2*W_QKV)
#define O_CQKV  (O_PROJ + 2*W_PROJ)
#define O_CPROJ (O_CQKV + 2*W_CQKV)
#define O_CPFC1 (O_CPROJ+ 2*W_CPROJ)
#define O_CPFC2 (O_CPFC1+ 2*W_CPFC1)
#define O_FC1   (O_CPFC2+ 2*W_CPFC2)
#define O_FC2   (O_FC1  + 2*W_FC1)
#define O_P     (O_FC2  + 2*W_FC2)
#define W_TOTAL (O_P    + 2*W_P)
__device__ bf16 g_wpool[W_TOTAL];

// ---------------------------------------------------------------------------
// Helpers
// ---------------------------------------------------------------------------
__device__ __forceinline__ void fsplit(float v, bf16& h, bf16& l) {
    h = __float2bfloat16(v);
    l = __float2bfloat16(v - __bfloat162float(h));
}

__device__ __forceinline__ unsigned pk2(bf16 a, bf16 b) {
    bf162 v = __halves2bfloat162(a, b);
    return *reinterpret_cast<unsigned*>(&v);
}

__device__ __forceinline__ float blk_sum(float v, float* sbuf) {
    #pragma unroll
    for (int o = 16; o; o >>= 1) v += __shfl_xor_sync(0xffffffffu, v, o);
    if ((threadIdx.x & 31) == 0) sbuf[threadIdx.x >> 5] = v;
    __syncthreads();
    if (threadIdx.x == 0) {
        float r = sbuf[0];
        int nw = blockDim.x >> 5;
        for (int i = 1; i < nw; i++) r += sbuf[i];
        sbuf[0] = r;
    }
    __syncthreads();
    float r = sbuf[0];
    __syncthreads();
    return r;
}

__global__ void split_k(const float* __restrict__ src, bf16* __restrict__ hi,
                        bf16* __restrict__ lo, int n) {
    for (int i = blockIdx.x * blockDim.x + threadIdx.x; i < n; i += gridDim.x * blockDim.x) {
        float v = src[i];
        bf16 h, l; fsplit(v, h, l);
        hi[i] = h; lo[i] = l;
    }
}

__global__ void ln_kernel(const float* __restrict__ x, const float* __restrict__ g,
                          const float* __restrict__ b, bf16* __restrict__ outh,
                          bf16* __restrict__ outl, float* __restrict__ rinv) {
    __shared__ float sbuf[8];
    long long row = blockIdx.x;
    const float* xr = x + row * DIMC;
    float v[3];
    float s = 0.f;
    #pragma unroll
    for (int k = 0; k < 3; k++) { v[k] = xr[threadIdx.x + 256 * k]; s += v[k]; }
    float mu = blk_sum(s, sbuf) * (1.f / DIMC);
    float s2 = 0.f;
    #pragma unroll
    for (int k = 0; k < 3; k++) { float d = v[k] - mu; s2 += d * d; }
    float var = blk_sum(s2, sbuf) * (1.f / DIMC);
    float rs = rsqrtf(var + 1e-5f);
    float sq = 0.f;
    #pragma unroll
    for (int k = 0; k < 3; k++) {
        int c = threadIdx.x + 256 * k;
        float yv = (v[k] - mu) * rs * g[c] + b[c];
        bf16 h, l; fsplit(yv, h, l);
        outh[row * DIMC + c] = h;
        outl[row * DIMC + c] = l;
        sq += yv * yv;
    }
    if (rinv) {
        float nn = blk_sum(sq, sbuf);
        if (threadIdx.x == 0) rinv[row] = 1.f / sqrtf(nn);
    }
}

__global__ void rownorm_kernel(const float* __restrict__ P, float* __restrict__ pinv) {
    __shared__ float sbuf[8];
    const float* r = P + (long long)blockIdx.x * DIMC;
    float s = 0.f;
    for (int k = threadIdx.x; k < DIMC; k += 256) { float v = r[k]; s += v * v; }
    s = blk_sum(s, sbuf);
    if (threadIdx.x == 0) pinv[blockIdx.x] = 1.f / sqrtf(s);
}

// ---------------------------------------------------------------------------
// MMA / ldmatrix / cp.async primitives
// ---------------------------------------------------------------------------
__device__ __forceinline__ void mma16816(float* d, const unsigned* a, const unsigned* b) {
    asm volatile(
        "mma.sync.aligned.m16n8k16.row.col.f32.bf16.bf16.f32 "
        "{%0,%1,%2,%3}, {%4,%5,%6,%7}, {%8,%9}, {%0,%1,%2,%3};\n"
        : "+f"(d[0]), "+f"(d[1]), "+f"(d[2]), "+f"(d[3])
        : "r"(a[0]), "r"(a[1]), "r"(a[2]), "r"(a[3]), "r"(b[0]), "r"(b[1]));
}

__device__ __forceinline__ void ldsm4(unsigned& r0, unsigned& r1, unsigned& r2,
                                      unsigned& r3, unsigned addr) {
    asm volatile("ldmatrix.sync.aligned.m8n8.x4.shared.b16 {%0,%1,%2,%3}, [%4];"
                 : "=r"(r0), "=r"(r1), "=r"(r2), "=r"(r3) : "r"(addr));
}

__device__ __forceinline__ void ldsm4t(unsigned& r0, unsigned& r1, unsigned& r2,
                                       unsigned& r3, unsigned addr) {
    asm volatile("ldmatrix.sync.aligned.m8n8.x4.trans.shared.b16 {%0,%1,%2,%3}, [%4];"
                 : "=r"(r0), "=r"(r1), "=r"(r2), "=r"(r3) : "r"(addr));
}

__device__ __forceinline__ void cpa16(unsigned saddr, const void* gaddr) {
    asm volatile("cp.async.cg.shared.global [%0], [%1], 16;\n"
                 :: "r"(saddr), "l"(gaddr));
}

// ---------------------------------------------------------------------------
// Fused flash attention (bf16x3, fp32 softmax).
// Grid: (NTOK/128, BATCH*HEADS). 8 warps; warp owns 16 Q rows.
// Q tile (128x64 hi/lo) resident; K/V (64x64 hi/lo) double-buffered cp.async.
// Smem (bf16 units): QH=0, QL=9216, stages at 18432 + s*18432:
//   KH=0, KL=4608, VH=9216, VL=13824 (row stride 72).
// ---------------------------------------------------------------------------
#define FL_SMEM_U (18432 + 2 * 18432)

__global__ void __launch_bounds__(256, 1)
flash_k(const bf16* __restrict__ qh_g, const bf16* __restrict__ ql_g,
        bf16* __restrict__ atth, bf16* __restrict__ attl) {
    extern __shared__ bf16 sm[];
    const unsigned u0 = (unsigned)__cvta_generic_to_shared(sm);
    const int tid = threadIdx.x, warp = tid >> 5, lane = tid & 31;
    const int g = lane >> 2, t = lane & 3;
    const int r16 = lane & 15, kh8 = (lane >> 4) * 8;
    const int wm0 = warp * 16;
    const int bx = blockIdx.x, bz = blockIdx.y;
    const int zb = bz / HEADS, zh = bz % HEADS;
    const int ldq = 3 * DIMC;
    const long long base = (long long)zb * NTOK * ldq + zh * HD;
    const bf16* Qh = qh_g + base + (long long)bx * 128 * ldq;
    const bf16* Ql = ql_g + base + (long long)bx * 128 * ldq;
    const bf16* KhG = qh_g + DIMC + base;
    const bf16* KlG = ql_g + DIMC + base;
    const bf16* VhG = qh_g + 2 * DIMC + base;
    const bf16* VlG = ql_g + 2 * DIMC + base;

    // Q fill (part of group 0)
    #pragma unroll
    for (int idx = tid; idx < 128 * 8; idx += 256) {
        int row = idx >> 3, c8 = (idx & 7) * 8;
        unsigned so = (unsigned)(row * 72 + c8) * 2u;
        cpa16(u0 + so, Qh + (long long)row * ldq + c8);
        cpa16(u0 + 9216 * 2u + so, Ql + (long long)row * ldq + c8);
    }
    auto fillKV = [&](int st, int kv0) {
        unsigned sb = u0 + (unsigned)(18432 + st * 18432) * 2u;
        #pragma unroll
        for (int idx = tid; idx < 64 * 8; idx += 256) {
            int row = idx >> 3, c8 = (idx & 7) * 8;
            long long go = (long long)(kv0 + row) * ldq + c8;
            unsigned so = (unsigned)(row * 72 + c8) * 2u;
            cpa16(sb + so,               KhG + go);
            cpa16(sb + 4608 * 2u + so,   KlG + go);
            cpa16(sb + 9216 * 2u + so,   VhG + go);
            cpa16(sb + 13824 * 2u + so,  VlG + go);
        }
        asm volatile("cp.async.commit_group;\n");
    };
    fillKV(0, 0);   // commit group 0 = Q + KV0

    float m0 = -1e30f, m1 = -1e30f, l0 = 0.f, l1 = 0.f;
    float accO[8][4] = {};

    for (int it = 0; it < NTOK / 64; it++) {
        if (it + 1 < NTOK / 64) {
            fillKV((it + 1) & 1, (it + 1) * 64);
            asm volatile("cp.async.wait_group 1;\n");
        } else {
            asm volatile("cp.async.wait_group 0;\n");
        }
        __syncthreads();
        const unsigned sb = u0 + (unsigned)(18432 + (it & 1) * 18432) * 2u;

        // ---- S = Q K^T (bf16x3) ----
        float accS[8][4] = {};
        #pragma unroll
        for (int ks = 0; ks < 4; ks++) {
            unsigned qa[4], qb[4], kf[8][2], kf2[8][2];
            unsigned qaddr = u0 + (unsigned)((wm0 + r16) * 72 + ks * 16 + kh8) * 2u;
            ldsm4(qa[0], qa[1], qa[2], qa[3], qaddr);
            ldsm4(qb[0], qb[1], qb[2], qb[3], qaddr + 9216 * 2u);
            #pragma unroll
            for (int nb = 0; nb < 4; nb++) {
                unsigned q0, q1, q2, q3;
                unsigned kaddr = sb + (unsigned)((nb * 16 + r16) * 72 + ks * 16 + kh8) * 2u;
                ldsm4(q0, q1, q2, q3, kaddr);
                kf[2*nb][0] = q0; kf[2*nb+1][0] = q1;
                kf[2*nb][1] = q2; kf[2*nb+1][1] = q3;
                ldsm4(q0, q1, q2, q3, kaddr + 4608 * 2u);
                kf2[2*nb][0] = q0; kf2[2*nb+1][0] = q1;
                kf2[2*nb][1] = q2; kf2[2*nb+1][1] = q3;
            }
            #pragma unroll
            for (int fn = 0; fn < 8; fn++) mma16816(accS[fn], qa, kf[fn]);   // hi*hi
            #pragma unroll
            for (int fn = 0; fn < 8; fn++) mma16816(accS[fn], qa, kf2[fn]);  // hi*lo
            #pragma unroll
            for (int fn = 0; fn < 8; fn++) mma16816(accS[fn], qb, kf[fn]);   // lo*hi
        }

        // ---- online softmax (rows owned by quad: shfl over t bits) ----
        float mx0 = -1e30f, mx1 = -1e30f;
        #pragma unroll
        for (int fn = 0; fn < 8; fn++) {
            #pragma unroll
            for (int j = 0; j < 4; j++) accS[fn][j] *= 0.125f;
            mx0 = fmaxf(mx0, fmaxf(accS[fn][0], accS[fn][1]));
            mx1 = fmaxf(mx1, fmaxf(accS[fn][2], accS[fn][3]));
        }
        mx0 = fmaxf(mx0, __shfl_xor_sync(0xffffffffu, mx0, 1));
        mx0 = fmaxf(mx0, __shfl_xor_sync(0xffffffffu, mx0, 2));
        mx1 = fmaxf(mx1, __shfl_xor_sync(0xffffffffu, mx1, 1));
        mx1 = fmaxf(mx1, __shfl_xor_sync(0xffffffffu, mx1, 2));
        float mn0 = fmaxf(m0, mx0), mn1 = fmaxf(m1, mx1);
        float sc0 = expf(m0 - mn0), sc1 = expf(m1 - mn1);
        m0 = mn0; m1 = mn1;

        float rs0 = 0.f, rs1 = 0.f;
        unsigned PaH[4][4], PaL[4][4];
        #pragma unroll
        for (int fn = 0; fn < 8; fn++) {
            float p0 = expf(accS[fn][0] - mn0);
            float p1 = expf(accS[fn][1] - mn0);
            float p2 = expf(accS[fn][2] - mn1);
            float p3 = expf(accS[fn][3] - mn1);
            rs0 += p0 + p1; rs1 += p2 + p3;
            bf16 h0, o0, h1, o1, h2, o2, h3, o3;
            fsplit(p0, h0, o0); fsplit(p1, h1, o1);
            fsplit(p2, h2, o2); fsplit(p3, h3, o3);
            int ks = fn >> 1, half = fn & 1;
            PaH[ks][half * 2 + 0] = pk2(h0, h1);
            PaH[ks][half * 2 + 1] = pk2(h2, h3);
            PaL[ks][half * 2 + 0] = pk2(o0, o1);
            PaL[ks][half * 2 + 1] = pk2(o2, o3);
        }
        rs0 += __shfl_xor_sync(0xffffffffu, rs0, 1);
        rs0 += __shfl_xor_sync(0xffffffffu, rs0, 2);
        rs1 += __shfl_xor_sync(0xffffffffu, rs1, 1);
        rs1 += __shfl_xor_sync(0xffffffffu, rs1, 2);
        l0 = l0 * sc0 + rs0;
        l1 = l1 * sc1 + rs1;
        #pragma unroll
        for (int fn = 0; fn < 8; fn++) {
            accO[fn][0] *= sc0; accO[fn][1] *= sc0;
            accO[fn][2] *= sc1; accO[fn][3] *= sc1;
        }

        // ---- O += P V (bf16x3; V frags via trans ldmatrix) ----
        const int koff = ((lane >> 4) & 1) * 8;
        const int noff = ((lane >> 3) & 1) * 8;
        #pragma unroll
        for (int ks = 0; ks < 4; ks++) {
            unsigned vf[8][2], vf2[8][2];
            #pragma unroll
            for (int nb = 0; nb < 4; nb++) {
                unsigned q0, q1, q2, q3;
                unsigned vaddr = sb + 9216 * 2u
                    + (unsigned)(((lane & 7) + koff + ks * 16) * 72 + nb * 16 + noff) * 2u;
                ldsm4t(q0, q1, q2, q3, vaddr);
                vf[2*nb][0] = q0; vf[2*nb+1][0] = q1;
                vf[2*nb][1] = q2; vf[2*nb+1][1] = q3;
                ldsm4t(q0, q1, q2, q3, vaddr + 4608 * 2u);
                vf2[2*nb][0] = q0; vf2[2*nb+1][0] = q1;
                vf2[2*nb][1] = q2; vf2[2*nb+1][1] = q3;
            }
            #pragma unroll
            for (int fn = 0; fn < 8; fn++) mma16816(accO[fn], PaH[ks], vf[fn]);
            #pragma unroll
            for (int fn = 0; fn < 8; fn++) mma16816(accO[fn], PaL[ks], vf[fn]);
            #pragma unroll
            for (int fn = 0; fn < 8; fn++) mma16816(accO[fn], PaH[ks], vf2[fn]);
        }
        __syncthreads();
    }

    // ---- write normalized O as bf16 pair ----
    float li0 = 1.f / l0, li1 = 1.f / l1;
    int tok0 = zb * NTOK + bx * 128 + wm0 + g;
    #pragma unroll
    for (int fn = 0; fn < 8; fn++) {
        int col = zh * HD + fn * 8 + t * 2;
        long long ix0 = (long long)tok0 * DIMC + col;
        long long ix1 = (long long)(tok0 + 8) * DIMC + col;
        float v0 = accO[fn][0] * li0, v1 = accO[fn][1] * li0;
        float w0 = accO[fn][2] * li1, w1 = accO[fn][3] * li1;
        bf16 h0, o0, h1, o1;
        fsplit(v0, h0, o0); fsplit(v1, h1, o1);
        *(bf162*)&atth[ix0] = __halves2bfloat162(h0, h1);
        *(bf162*)&attl[ix0] = __halves2bfloat162(o0, o1);
        fsplit(w0, h0, o0); fsplit(w1, h1, o1);
        *(bf162*)&atth[ix1] = __halves2bfloat162(h0, h1);
        *(bf162*)&attl[ix1] = __halves2bfloat162(o0, o1);
    }
}

static void run_flash(const bf16* qh, const bf16* ql, bf16* ah, bf16* al) {
    constexpr int SMEM = FL_SMEM_U * 2;
    cudaFuncSetAttribute((const void*)flash_k,
                         cudaFuncAttributeMaxDynamicSharedMemorySize, SMEM);
    dim3 grid(NTOK / 128, BATCH * HEADS);
    flash_k<<<grid, 256, SMEM>>>(qh, ql, ah, al);
}

// ---------------------------------------------------------------------------
// Pipelined (2-stage cp.async) pair-input bf16x3 tensor-core GEMM.
// ---------------------------------------------------------------------------
template<int BM, int BN, int BK, int WGM, int WGN, int WM, int WN, bool TRB, int EPI, int OUTM>
__global__ void __launch_bounds__(WGM * WGN * 32, 2)
pgemm_k(const bf16* __restrict__ Ahi, const bf16* __restrict__ Alo,
        const bf16* __restrict__ Bhi, const bf16* __restrict__ Blo,
        float* __restrict__ Cf, bf16* __restrict__ Chi, bf16* __restrict__ Clo,
        int K, int lda, int ldb, int ldc,
        float alpha, const float* __restrict__ bias,
        const float* __restrict__ res1, const float* __restrict__ res2,
        const float* __restrict__ rowscale, const float* __restrict__ colscale) {
    constexpr int NT = WGM * WGN * 32;
    constexpr int MF = WM / 16;
    constexpr int NF = WN / 8;
    constexpr int NB = WN / 16;
    constexpr int KP = BK + 8;
    constexpr int BNP = BN + 8;
    constexpr int ASZ = BM * KP;
    constexpr int BSZ = TRB ? (BN * KP) : (BK * BNP);
    constexpr unsigned STGB = (unsigned)(2 * ASZ + 2 * BSZ) * 2u;
    constexpr unsigned OFF_AH = 0;
    constexpr unsigned OFF_AL = (unsigned)ASZ * 2u;
    constexpr unsigned OFF_BH = (unsigned)ASZ * 4u;
    constexpr unsigned OFF_BL = (unsigned)ASZ * 4u + (unsigned)BSZ * 2u;
    static_assert(WGM * WM == BM && WGN * WN == BN && (WN % 16) == 0, "tile");

    extern __shared__ bf16 smem_dyn[];
    const unsigned u0 = (unsigned)__cvta_generic_to_shared(smem_dyn);

    const int tid = threadIdx.x;
    const int warp = tid >> 5, lane = tid & 31;
    const int g = lane >> 2, t = lane & 3;
    const int r16 = lane & 15, kh = (lane >> 4) * 8;
    const int wm0 = (warp / WGN) * WM, wn0 = (warp % WGN) * WN;
    const int bx = blockIdx.x, by = blockIdx.y;

    const long long aoff = (long long)by * BM * lda;
    const long long boff = TRB ? (long long)bx * BN * ldb : (long long)(bx * BN);
    const long long coff = (long long)by * BM * ldc + (long long)(bx * BN);

    const bf16* Abh = Ahi + aoff; const bf16* Abl = Alo + aoff;
    const bf16* Bbh = Bhi + boff; const bf16* Bbl = Blo + boff;

    unsigned aoffs[MF], boffs[NB];
    #pragma unroll
    for (int fm = 0; fm < MF; fm++)
        aoffs[fm] = (unsigned)((wm0 + fm * 16 + r16) * KP + kh) * 2u;
    if constexpr (TRB) {
        #pragma unroll
        for (int nb = 0; nb < NB; nb++)
            boffs[nb] = (unsigned)((wn0 + nb * 16 + r16) * KP + kh) * 2u;
    } else {
        const int koff = ((lane >> 4) & 1) * 8;
        const int noff = ((lane >> 3) & 1) * 8;
        #pragma unroll
        for (int nb = 0; nb < NB; nb++)
            boffs[nb] = (unsigned)(((lane & 7) + koff) * BNP + wn0 + nb * 16 + noff) * 2u;
    }

    float acc[MF][NF][4] = {};
    const int NKS = K / BK;

    auto fill = [&](int st, int k0) {
        const unsigned stb = u0 + (unsigned)st * STGB;
        #pragma unroll
        for (int idx = tid; idx < BM * (BK / 8); idx += NT) {
            int row = idx / (BK / 8), c8 = idx % (BK / 8);
            long long go = (long long)row * lda + k0 + 8 * c8;
            unsigned so = (unsigned)(row * KP + 8 * c8) * 2u;
            cpa16(stb + OFF_AH + so, Abh + go);
            cpa16(stb + OFF_AL + so, Abl + go);
        }
        if constexpr (TRB) {
            #pragma unroll
            for (int idx = tid; idx < BN * (BK / 8); idx += NT) {
                int row = idx / (BK / 8), c8 = idx % (BK / 8);
                long long go = (long long)row * ldb + k0 + 8 * c8;
                unsigned so = (unsigned)(row * KP + 8 * c8) * 2u;
                cpa16(stb + OFF_BH + so, Bbh + go);
                cpa16(stb + OFF_BL + so, Bbl + go);
            }
        } else {
            #pragma unroll
            for (int idx = tid; idx < BK * (BN / 8); idx += NT) {
                int kr = idx / (BN / 8), c8 = idx % (BN / 8);
                long long go = (long long)(k0 + kr) * ldb + 8 * c8;
                unsigned so = (unsigned)(kr * BNP + 8 * c8) * 2u;
                cpa16(stb + OFF_BH + so, Bbh + go);
                cpa16(stb + OFF_BL + so, Bbl + go);
            }
        }
        asm volatile("cp.async.commit_group;\n");
    };

    fill(0, 0);
    for (int i = 0; i < NKS; i++) {
        if (i + 1 < NKS) {
            fill((i + 1) & 1, (i + 1) * BK);
            asm volatile("cp.async.wait_group 1;\n");
        } else {
            asm volatile("cp.async.wait_group 0;\n");
        }
        __syncthreads();

        const unsigned stb = u0 + (unsigned)(i & 1) * STGB;
        #pragma unroll
        for (int ks = 0; ks < BK / 16; ks++) {
            const unsigned kbA = (unsigned)ks * 32u;
            unsigned Ar[MF][4], Bf[NF][2], Bf2[NF][2];
            #pragma unroll
            for (int fm = 0; fm < MF; fm++)
                ldsm4(Ar[fm][0], Ar[fm][1], Ar[fm][2], Ar[fm][3],
                      stb + OFF_AH + aoffs[fm] + kbA);
            #pragma unroll
            for (int nb = 0; nb < NB; nb++) {
                unsigned q0, q1, q2, q3;
                if constexpr (TRB)
                    ldsm4(q0, q1, q2, q3, stb + OFF_BH + boffs[nb] + kbA);
                else
                    ldsm4t(q0, q1, q2, q3, stb + OFF_BH + boffs[nb]
                           + (unsigned)(ks * 16 * BNP) * 2u);
                Bf[2*nb][0] = q0; Bf[2*nb+1][0] = q1;
                Bf[2*nb][1] = q2; Bf[2*nb+1][1] = q3;
            }
            #pragma unroll
            for (int fm = 0; fm < MF; fm++)
                #pragma unroll
                for (int fn = 0; fn < NF; fn++)
                    mma16816(acc[fm][fn], Ar[fm], Bf[fn]);
            #pragma unroll
            for (int nb = 0; nb < NB; nb++) {
                unsigned q0, q1, q2, q3;
                if constexpr (TRB)
                    ldsm4(q0, q1, q2, q3, stb + OFF_BL + boffs[nb] + kbA);
                else
                    ldsm4t(q0, q1, q2, q3, stb + OFF_BL + boffs[nb]
                           + (unsigned)(ks * 16 * BNP) * 2u);
                Bf2[2*nb][0] = q0; Bf2[2*nb+1][0] = q1;
                Bf2[2*nb][1] = q2; Bf2[2*nb+1][1] = q3;
            }
            #pragma unroll
            for (int fm = 0; fm < MF; fm++)
                #pragma unroll
                for (int fn = 0; fn < NF; fn++)
                    mma16816(acc[fm][fn], Ar[fm], Bf2[fn]);
            #pragma unroll
            for (int fm = 0; fm < MF; fm++)
                ldsm4(Ar[fm][0], Ar[fm][1], Ar[fm][2], Ar[fm][3],
                      stb + OFF_AL + aoffs[fm] + kbA);
            #pragma unroll
            for (int fm = 0; fm < MF; fm++)
                #pragma unroll
                for (int fn = 0; fn < NF; fn++)
                    mma16816(acc[fm][fn], Ar[fm], Bf[fn]);
        }
        __syncthreads();
    }

    #pragma unroll
    for (int fm = 0; fm < MF; fm++) {
        #pragma unroll
        for (int fn = 0; fn < NF; fn++) {
            #pragma unroll
            for (int hh = 0; hh < 2; hh++) {
                int lrow = wm0 + fm * 16 + g + hh * 8;
                long long m = (long long)by * BM + lrow;
                int lcol = wn0 + fn * 8 + t * 2;
                int n = bx * BN + lcol;
                float v0 = acc[fm][fn][hh * 2 + 0] * alpha;
                float v1 = acc[fm][fn][hh * 2 + 1] * alpha;
                if (bias) { v0 += bias[n]; v1 += bias[n + 1]; }
                if constexpr (EPI == 1) {
                    v0 = 0.5f * v0 * (1.f + erff(v0 * 0.70710678118654752f));
                    v1 = 0.5f * v1 * (1.f + erff(v1 * 0.70710678118654752f));
                }
                if constexpr (EPI == 2) {
                    float rsc = rowscale[m];
                    v0 *= rsc * colscale[n];
                    v1 *= rsc * colscale[n + 1];
                }
                long long cix = coff + (long long)lrow * ldc + lcol;
                if constexpr (EPI == 3) {
                    v0 += res1[cix]; v1 += res1[cix + 1];
                    if (res2) { v0 += res2[cix]; v1 += res2[cix + 1]; }
                }
                if constexpr (OUTM == 0 || OUTM == 2) {
                    float2 fv = make_float2(v0, v1);
                    *(float2*)&Cf[cix] = fv;
                }
                if constexpr (OUTM >= 1) {
                    bf16 h0, l0, h1, l1;
                    fsplit(v0, h0, l0); fsplit(v1, h1, l1);
                    *(bf162*)&Chi[cix] = __halves2bfloat162(h0, h1);
                    *(bf162*)&Clo[cix] = __halves2bfloat162(l0, l1);
                }
            }
        }
    }
}

template<bool TRB, int EPI, int OUTM>
static void run128(const bf16* Ah, const bf16* Al, const bf16* Bh, const bf16* Bl,
                   float* Cf, bf16* Chi, bf16* Clo,
                   int Mrows, int Ncols, int K, int lda, int ldb, int ldc,
                   float alpha, const float* bias, const float* res1, const float* res2,
                   const float* rs, const float* cs) {
    auto kfn = pgemm_k<128, 128, 32, 2, 4, 64, 32, TRB, EPI, OUTM>;
    constexpr int ASZ = 128 * 40;
    constexpr int BSZ = TRB ? (128 * 40) : (32 * 136);
    constexpr int SMEM = 2 * (2 * ASZ + 2 * BSZ) * 2;
    cudaFuncSetAttribute((const void*)kfn,
                         cudaFuncAttributeMaxDynamicSharedMemorySize, SMEM);
    dim3 grid(Ncols / 128, Mrows / 128);
    kfn<<<grid, 256, SMEM>>>(
        Ah, Al, Bh, Bl, Cf, Chi, Clo, K, lda, ldb, ldc,
        alpha, bias, res1, res2, rs, cs);
}

template<bool TRB, int EPI, int OUTM>
static void run64(const bf16* Ah, const bf16* Al, const bf16* Bh, const bf16* Bl,
                  float* Cf, bf16* Chi, bf16* Clo,
                  int Mrows, int Ncols, int K, int lda, int ldb, int ldc,
                  float alpha, const float* bias, const float* res1, const float* res2,
                  const float* rs, const float* cs) {
    auto kfn = pgemm_k<128, 64, 32, 2, 4, 64, 16, TRB, EPI, OUTM>;
    constexpr int ASZ = 128 * 40;
    constexpr int BSZ = TRB ? (64 * 40) : (32 * 72);
    constexpr int SMEM = 2 * (2 * ASZ + 2 * BSZ) * 2;
    cudaFuncSetAttribute((const void*)kfn,
                         cudaFuncAttributeMaxDynamicSharedMemorySize, SMEM);
    dim3 grid(Ncols / 64, Mrows / 128);
    kfn<<<grid, 256, SMEM>>>(
        Ah, Al, Bh, Bl, Cf, Chi, Clo, K, lda, ldb, ldc,
        alpha, bias, res1, res2, rs, cs);
}

// ---------------------------------------------------------------------------
// kernel_launch
// ---------------------------------------------------------------------------
extern "C" void kernel_launch(void* const* d_in, const int* in_sizes, int n_in,
                              void* d_out, int out_size) {
    const float* x        = (const float*)d_in[0];
    const float* ln1_g    = (const float*)d_in[1];
    const float* ln1_b    = (const float*)d_in[2];
    const float* qkv_w    = (const float*)d_in[3];
    const float* qkv_b    = (const float*)d_in[4];
    const float* proj_w   = (const float*)d_in[5];
    const float* proj_b   = (const float*)d_in[6];
    const float* c_qkv_w  = (const float*)d_in[7];
    const float* c_qkv_b  = (const float*)d_in[8];
    const float* c_proj_w = (const float*)d_in[9];
    const float* c_proj_b = (const float*)d_in[10];
    const float* cp_fc1_w = (const float*)d_in[11];
    const float* cp_fc1_b = (const float*)d_in[12];
    const float* cp_fc2_w = (const float*)d_in[13];
    const float* cp_fc2_b = (const float*)d_in[14];
    const float* P        = (const float*)d_in[15];
    const float* ln2_g    = (const float*)d_in[16];
    const float* ln2_b    = (const float*)d_in[17];
    const float* fc1_w    = (const float*)d_in[18];
    const float* fc1_b    = (const float*)d_in[19];
    const float* fc2_w    = (const float*)d_in[20];
    const float* fc2_b    = (const float*)d_in[21];

    float *y, *xr, *rinv, *pinv;
    bf16 *n1p, *qkvp, *attp, *h1p, *zinp, *hp, *dmp, *wpool;
    cudaGetSymbolAddress((void**)&y,      g_y);
    cudaGetSymbolAddress((void**)&xr,     g_xr);
    cudaGetSymbolAddress((void**)&rinv,   g_rinv);
    cudaGetSymbolAddress((void**)&pinv,   g_pinv);
    cudaGetSymbolAddress((void**)&n1p,    g_n1p);
    cudaGetSymbolAddress((void**)&qkvp,   g_qkvp);
    cudaGetSymbolAddress((void**)&attp,   g_attp);
    cudaGetSymbolAddress((void**)&h1p,    g_h1p);
    cudaGetSymbolAddress((void**)&zinp,   g_zinp);
    cudaGetSymbolAddress((void**)&hp,     g_hp);
    cudaGetSymbolAddress((void**)&dmp,    g_dmp);
    cudaGetSymbolAddress((void**)&wpool,  g_wpool);

    bf16 *wqh = wpool + O_QKV,   *wql = wqh + W_QKV;
    bf16 *wph = wpool + O_PROJ,  *wpl = wph + W_PROJ;
    bf16 *wch = wpool + O_CQKV,  *wcl = wch + W_CQKV;
    bf16 *wcph = wpool + O_CPROJ,*wcpl = wcph + W_CPROJ;
    bf16 *wf1h = wpool + O_CPFC1,*wf1l = wf1h + W_CPFC1;
    bf16 *wf2h = wpool + O_CPFC2,*wf2l = wf2h + W_CPFC2;
    bf16 *wm1h = wpool + O_FC1,  *wm1l = wm1h + W_FC1;
    bf16 *wm2h = wpool + O_FC2,  *wm2l = wm2h + W_FC2;
    bf16 *wPh = wpool + O_P,     *wPl = wPh + W_P;

    bf16 *n1h = n1p,  *n1l = n1p + MTOK * DIMC;
    bf16 *qkvh = qkvp,*qkvl = qkvp + MTOK * 3 * DIMC;
    bf16 *atth = attp,*attl = attp + MTOK * DIMC;
    bf16 *h1h = h1p,  *h1l = h1p + MTOK * KPARTS;
    bf16 *zinh = zinp,*zinl = zinp + MTOK * DIMC;
    bf16 *hh = hp,    *hl = hp + MTOK * MLPH;
    bf16 *dmh = dmp,  *dml = dmp + MTOK * KPARTS;

    float* out_x = (float*)d_out;
    float* dmap  = (float*)d_out + X_ELEMS;

    // ---- weight splits ----
    split_k<<<512, 256>>>(qkv_w,    wqh,  wql,  W_QKV);
    split_k<<<256, 256>>>(proj_w,   wph,  wpl,  W_PROJ);
    split_k<<<512, 256>>>(c_qkv_w,  wch,  wcl,  W_CQKV);
    split_k<<<256, 256>>>(c_proj_w, wcph, wcpl, W_CPROJ);
    split_k<<<16,  256>>>(cp_fc1_w, wf1h, wf1l, W_CPFC1);
    split_k<<<64,  256>>>(cp_fc2_w, wf2h, wf2l, W_CPFC2);
    split_k<<<512, 256>>>(fc1_w,    wm1h, wm1l, W_FC1);
    split_k<<<512, 256>>>(fc2_w,    wm2h, wm2l, W_FC2);
    split_k<<<64,  256>>>(P,        wPh,  wPl,  W_P);

    // 1. LN1 -> n1 pair + rinv;  2. pinv
    ln_kernel<<<MTOK, 256>>>(x, ln1_g, ln1_b, n1h, n1l, rinv);
    rownorm_kernel<<<KPARTS, 256>>>(P, pinv);

    // 3. qkv = n1 @ qkv_w^T + b  -> pair
    run128<true, 0, 1>(n1h, n1l, wqh, wql, nullptr, qkvh, qkvl,
        MTOK, 3 * DIMC, DIMC, DIMC, DIMC, 3 * DIMC,
        1.f, qkv_b, nullptr, nullptr, nullptr, nullptr);

    // 4. fused flash attention #1 -> att pair
    run_flash(qkvh, qkvl, atth, attl);

    // 5. y = att @ proj_w^T + b  (fp32)
    run128<true, 0, 0>(atth, attl, wph, wpl, y, nullptr, nullptr,
        MTOK, DIMC, DIMC, DIMC, DIMC, DIMC,
        1.f, proj_b, nullptr, nullptr, nullptr, nullptr);
    // 6. dmap = cosine(n1, P) -> fp32 out + pair
    run64<true, 2, 2>(n1h, n1l, wPh, wPl, dmap, dmh, dml,
        MTOK, KPARTS, DIMC, DIMC, DIMC, KPARTS,
        1.f, nullptr, nullptr, nullptr, rinv, pinv);
    // 7. h1 = gelu(dmap @ cp_fc1_w^T + b) -> pair
    run64<true, 1, 1>(dmh, dml, wf1h, wf1l, nullptr, h1h, h1l,
        MTOK, KPARTS, KPARTS, KPARTS, KPARTS, KPARTS,
        1.f, cp_fc1_b, nullptr, nullptr, nullptr, nullptr);
    // 8. zin = h1 @ cp_fc2_w^T + b -> pair
    run128<true, 0, 1>(h1h, h1l, wf2h, wf2l, nullptr, zinh, zinl,
        MTOK, DIMC, KPARTS, KPARTS, KPARTS, DIMC,
        1.f, cp_fc2_b, nullptr, nullptr, nullptr, nullptr);
    // 9. c_qkv -> pair (reuse qkv)
    run128<true, 0, 1>(zinh, zinl, wch, wcl, nullptr, qkvh, qkvl,
        MTOK, 3 * DIMC, DIMC, DIMC, DIMC, 3 * DIMC,
        1.f, c_qkv_b, nullptr, nullptr, nullptr, nullptr);

    // 10. fused flash attention #2
    run_flash(qkvh, qkvl, atth, attl);

    // 11. xr = att @ c_proj_w^T + b + x + y
    run128<true, 3, 0>(atth, attl, wcph, wcpl, xr, nullptr, nullptr,
        MTOK, DIMC, DIMC, DIMC, DIMC, DIMC,
        1.f, c_proj_b, x, y, nullptr, nullptr);
    // 12. LN2 -> n1 pair
    ln_kernel<<<MTOK, 256>>>(xr, ln2_g, ln2_b, n1h, n1l, nullptr);
    // 13. h = gelu(n1 @ fc1_w^T + b) -> pair
    run128<true, 1, 1>(n1h, n1l, wm1h, wm1l, nullptr, hh, hl,
        MTOK, MLPH, DIMC, DIMC, DIMC, MLPH,
        1.f, fc1_b, nullptr, nullptr, nullptr, nullptr);
    // 14. out_x = h @ fc2_w^T + b + xr
    run128<true, 3, 0>(hh, hl, wm2h, wm2l, out_x, nullptr, nullptr,
        MTOK, DIMC, MLPH, MLPH, MLPH, DIMC,
        1.f, fc2_b, xr, nullptr, nullptr, nullptr);
}